// round 3
// baseline (speedup 1.0000x reference)
#include <cuda_runtime.h>

// ---------------------------------------------------------------------------
// Problem constants: B=64, S=20, E=512, H=512, V=32000, C=1000
//   D1 = 11264, virtual K1 = D1 + H = 11776, 4H = 2048
// ---------------------------------------------------------------------------
#define Bsz   64
#define Hdim  512
#define G4H   2048
#define Vdim  32000
#define K1v   11776   // [enc 10240 | word 512 | persona 512 | h0 512]

// Scratch (device globals — allocation-free per harness rules)
static __device__ float g_zpart[16 * Bsz * G4H];   // 8.4 MB (max 16 split slices)
static __device__ float g_hbuf[2][Bsz * Hdim];
static __device__ float g_cbuf[2][Bsz * Hdim];
static __device__ float g_logits[Bsz * Vdim];      // 8.2 MB (single slice)

// ---------------------------------------------------------------------------
// f32x2 packed helpers (FFMA2: 2x fp32 FMA throughput per issue slot)
// ---------------------------------------------------------------------------
__device__ __forceinline__ unsigned long long pack2(float lo, float hi) {
    unsigned long long r;
    asm("mov.b64 %0, {%1, %2};" : "=l"(r) : "f"(lo), "f"(hi));
    return r;
}
__device__ __forceinline__ void unpack2(unsigned long long v, float& lo, float& hi) {
    asm("mov.b64 {%0, %1}, %2;" : "=f"(lo), "=f"(hi) : "l"(v));
}
__device__ __forceinline__ void fma2(unsigned long long& d, unsigned long long a,
                                     unsigned long long b) {
    asm("fma.rn.f32x2 %0, %1, %2, %0;" : "+l"(d) : "l"(a), "l"(b));
}
__device__ __forceinline__ float sigmoidf_fast(float x) {
    return 1.0f / (1.0f + __expf(-x));
}

// ---------------------------------------------------------------------------
// Split-K partial GEMM, M=64 (batch), TILE_N=64, BK=16, 256 threads.
//   Zp[sp][m][n0+n] = sum_{k in [sp*kc, (sp+1)*kc)} Xv[m][k] * Wv[k][n0+n]
// Virtual X (per MODE):
//   MODE 0: plain X, row stride ldx                    (decoder)
//   MODE 1: [enc | word | persona[speaker] | h0]       (layer 1, K1v wide)
//   MODE 2: [h | h]  (col & 511)                       (layers 2-4, K=1024)
// Virtual W: rows < wsplit -> Wa, else Wb (row - wsplit). Both row-major, ld N.
// Per-thread micro-tile: 4 rows x 4 cols as 8 f32x2 accumulators.
// X in smem is pre-duplicated f32x2; inner loop = 3 LDS.128 + 8 FFMA2.
// ---------------------------------------------------------------------------
template<int MODE>
__global__ __launch_bounds__(256, 2) void gemm64_kernel(
    const float* __restrict__ X, int ldx,
    const float* __restrict__ Wa, const float* __restrict__ Wb, int wsplit,
    int kc, int N, float* __restrict__ Zp,
    const float* __restrict__ enc, const float* __restrict__ word,
    const float* __restrict__ persona, const int* __restrict__ speaker)
{
    __shared__ __align__(16) unsigned long long Xd[2][16][64];  // dup-packed X
    __shared__ __align__(16) float Ws[2][16][64];

    const int tid = threadIdx.x;
    const int tx = tid & 15;            // col group: cols tx*4 .. +3
    const int ty = tid >> 4;            // row group: rows ty*4 .. +3
    const int n0 = blockIdx.x * 64;
    const int sp = blockIdx.y;
    const int k0 = sp * kc;

    // ---- X loader mapping: thread -> (row xr, k sub-offset xq) ----
    const int xr = tid >> 2;            // 0..63
    const int xq = (tid & 3) * 4;       // 0,4,8,12

    const float *encp = nullptr, *wordp = nullptr, *persp = nullptr, *h0p = nullptr;
    const float *xbase = nullptr;
    if (MODE == 1) {
        int spk = speaker[xr];
        encp  = enc + (long long)xr * 10240;
        wordp = word + (long long)xr * 512 - 10240;
        persp = persona + (long long)spk * 512 - 10752;
        h0p   = X + (long long)xr * 512 - 11264;     // X carries h0 in MODE 1
    } else if (MODE == 2) {
        xbase = X + (long long)xr * 512;
    } else {
        xbase = X + (long long)xr * ldx;
    }

    auto load_x = [&](int t) -> float4 {
        int kg = k0 + xq + t * 16;
        if (MODE == 1) {
            const float* p = (kg < 10240) ? (encp + kg)
                           : (kg < 10752) ? (wordp + kg)
                           : (kg < 11264) ? (persp + kg)
                                          : (h0p + kg);
            return *reinterpret_cast<const float4*>(p);
        } else if (MODE == 2) {
            return *reinterpret_cast<const float4*>(xbase + (kg & 511));
        } else {
            return *reinterpret_cast<const float4*>(xbase + kg);
        }
    };

    // ---- W loader mapping: thread loads one float4 row slice ----
    const int wrow = tid >> 4;          // 0..15
    const int wc = (tid & 15) * 4;
    auto load_w = [&](int t) -> float4 {
        int r = k0 + t * 16 + wrow;
        const float* p = (r < wsplit)
            ? (Wa + (long long)r * N)
            : (Wb + (long long)(r - wsplit) * N);
        return *reinterpret_cast<const float4*>(p + n0 + wc);
    };

    // preload tile 0
    float4 px = load_x(0);
    float4 pw = load_w(0);
    Xd[0][xq + 0][xr] = pack2(px.x, px.x);
    Xd[0][xq + 1][xr] = pack2(px.y, px.y);
    Xd[0][xq + 2][xr] = pack2(px.z, px.z);
    Xd[0][xq + 3][xr] = pack2(px.w, px.w);
    *reinterpret_cast<float4*>(&Ws[0][wrow][wc]) = pw;
    __syncthreads();

    unsigned long long acc[4][2];
#pragma unroll
    for (int r = 0; r < 4; r++) { acc[r][0] = 0ULL; acc[r][1] = 0ULL; }

    const int ntiles = kc >> 4;
    int buf = 0;
    for (int t = 0; t < ntiles; t++) {
        const bool has_next = (t + 1 < ntiles);
        if (has_next) {
            px = load_x(t + 1);
            pw = load_w(t + 1);
        }
#pragma unroll
        for (int kk = 0; kk < 16; kk++) {
            ulonglong2 wv = *reinterpret_cast<const ulonglong2*>(&Ws[buf][kk][tx * 4]);
            ulonglong2 xa = *reinterpret_cast<const ulonglong2*>(&Xd[buf][kk][ty * 4 + 0]);
            ulonglong2 xb = *reinterpret_cast<const ulonglong2*>(&Xd[buf][kk][ty * 4 + 2]);
            fma2(acc[0][0], xa.x, wv.x); fma2(acc[0][1], xa.x, wv.y);
            fma2(acc[1][0], xa.y, wv.x); fma2(acc[1][1], xa.y, wv.y);
            fma2(acc[2][0], xb.x, wv.x); fma2(acc[2][1], xb.x, wv.y);
            fma2(acc[3][0], xb.y, wv.x); fma2(acc[3][1], xb.y, wv.y);
        }
        __syncthreads();
        if (has_next) {
            int nb = buf ^ 1;
            Xd[nb][xq + 0][xr] = pack2(px.x, px.x);
            Xd[nb][xq + 1][xr] = pack2(px.y, px.y);
            Xd[nb][xq + 2][xr] = pack2(px.z, px.z);
            Xd[nb][xq + 3][xr] = pack2(px.w, px.w);
            *reinterpret_cast<float4*>(&Ws[nb][wrow][wc]) = pw;
            buf = nb;
            __syncthreads();
        }
    }

    // epilogue: acc[r] -> row (ty*4 + r), cols tx*4 .. +3
    float* zbase = Zp + ((long long)sp * 64 + ty * 4) * N + n0 + tx * 4;
#pragma unroll
    for (int r = 0; r < 4; r++) {
        float c0, c1, c2, c3;
        unpack2(acc[r][0], c0, c1);
        unpack2(acc[r][1], c2, c3);
        *reinterpret_cast<float4*>(zbase + (long long)r * N) =
            make_float4(c0, c1, c2, c3);
    }
}

// ---------------------------------------------------------------------------
// Gate kernel: reduce NSL split-K slices + bias, apply Keras LSTM cell
//   (gate order i,f,g,o; activation=relu, recurrent_activation=sigmoid).
//   Compile-time NSL -> fully unrolled loads (high MLP).
// ---------------------------------------------------------------------------
template<int NSL>
__global__ void gates_kernel(const float* __restrict__ Zp,
                             const float* __restrict__ bias,
                             const float* __restrict__ c_prev,
                             float* __restrict__ h_new,
                             float* __restrict__ c_new,
                             float* __restrict__ h_mir,
                             float* __restrict__ c_mir)
{
    int idx = blockIdx.x * 128 + threadIdx.x;   // < 64*512
    if (idx >= Bsz * Hdim) return;
    int bt = idx >> 9;
    int j = idx & 511;
    float zi = bias[j], zf = bias[512 + j], zg = bias[1024 + j], zo = bias[1536 + j];
    const float* p = Zp + (long long)bt * G4H + j;
#pragma unroll
    for (int s = 0; s < NSL; s++) {
        const float* q = p + (long long)s * Bsz * G4H;
        zi += q[0];
        zf += q[512];
        zg += q[1024];
        zo += q[1536];
    }
    float cv = sigmoidf_fast(zf) * c_prev[idx] + sigmoidf_fast(zi) * fmaxf(zg, 0.0f);
    float hv = sigmoidf_fast(zo) * fmaxf(cv, 0.0f);
    c_new[idx] = cv;
    h_new[idx] = hv;
    if (h_mir) { h_mir[idx] = hv; c_mir[idx] = cv; }
}

// ---------------------------------------------------------------------------
// Softmax over V=32000 per batch row (single logits slice + bias).
// ---------------------------------------------------------------------------
__global__ void softmax_kernel(const float* __restrict__ L,
                               const float* __restrict__ bd,
                               float* __restrict__ out)
{
    const int V = Vdim;
    int b = blockIdx.x;
    int tid = threadIdx.x;
    const float* r0 = L + (long long)b * V;

    float m = -1e30f, s = 0.0f;
    for (int v = tid; v < V; v += 512) {
        float val = r0[v] + bd[v];
        float nm = fmaxf(m, val);
        s = s * __expf(m - nm) + __expf(val - nm);
        m = nm;
    }
    __shared__ float sm[512], ss[512];
    sm[tid] = m;
    ss[tid] = s;
    __syncthreads();
    for (int st = 256; st > 0; st >>= 1) {
        if (tid < st) {
            float m2 = sm[tid + st], s2 = ss[tid + st];
            float nm = fmaxf(sm[tid], m2);
            ss[tid] = ss[tid] * __expf(sm[tid] - nm) + s2 * __expf(m2 - nm);
            sm[tid] = nm;
        }
        __syncthreads();
    }
    float M = sm[0];
    float Sinv = 1.0f / ss[0];
    for (int v = tid; v < V; v += 512) {
        float val = r0[v] + bd[v];
        out[(long long)b * V + v] = __expf(val - M) * Sinv;
    }
}

// ---------------------------------------------------------------------------
// kernel_launch
// ---------------------------------------------------------------------------
extern "C" void kernel_launch(void* const* d_in, const int* in_sizes, int n_in,
                              void* d_out, int out_size)
{
    const float* enc     = (const float*)d_in[0];
    const float* word    = (const float*)d_in[1];
    const float* h0      = (const float*)d_in[2];
    const float* c0      = (const float*)d_in[3];
    const float* persona = (const float*)d_in[4];
    const float* W1      = (const float*)d_in[5];
    const float* U1      = (const float*)d_in[6];
    const float* b1      = (const float*)d_in[7];
    const float* W2      = (const float*)d_in[8];
    const float* U2      = (const float*)d_in[9];
    const float* b2      = (const float*)d_in[10];
    const float* W3      = (const float*)d_in[11];
    const float* U3      = (const float*)d_in[12];
    const float* b3      = (const float*)d_in[13];
    const float* W4      = (const float*)d_in[14];
    const float* U4      = (const float*)d_in[15];
    const float* b4      = (const float*)d_in[16];
    const float* Wd      = (const float*)d_in[17];
    const float* bd      = (const float*)d_in[18];
    const int*   speaker = (const int*)d_in[19];
    float* out = (float*)d_out;

    void *pz, *ph, *pc, *pl;
    cudaGetSymbolAddress(&pz, g_zpart);
    cudaGetSymbolAddress(&ph, g_hbuf);
    cudaGetSymbolAddress(&pc, g_cbuf);
    cudaGetSymbolAddress(&pl, g_logits);
    float* zp = (float*)pz;
    float* hb = (float*)ph;
    float* cb = (float*)pc;
    float* lg = (float*)pl;
    float* h1b = hb;
    float* h2b = hb + Bsz * Hdim;
    float* c1b = cb;
    float* c2b = cb + Bsz * Hdim;

    const int GATE_GRID = (Bsz * Hdim) / 128;   // 256 blocks of 128

    // layer 1: z = [x|h0] @ [W1;U1], K=11776, 16 splits of 736, grid 32x16=512
    gemm64_kernel<1><<<dim3(32, 16), 256>>>(
        h0, 0, W1, U1, 11264, 736, G4H, zp, enc, word, persona, speaker);
    gates_kernel<16><<<GATE_GRID, 128>>>(zp, b1, c0, h1b, c1b, nullptr, nullptr);

    // layers 2..4: z = [h|h] @ [W;U], K=1024, 8 splits of 128, grid 32x8=256
    gemm64_kernel<2><<<dim3(32, 8), 256>>>(
        h1b, 0, W2, U2, 512, 128, G4H, zp, nullptr, nullptr, nullptr, nullptr);
    gates_kernel<8><<<GATE_GRID, 128>>>(zp, b2, c1b, h2b, c2b, nullptr, nullptr);

    gemm64_kernel<2><<<dim3(32, 8), 256>>>(
        h2b, 0, W3, U3, 512, 128, G4H, zp, nullptr, nullptr, nullptr, nullptr);
    gates_kernel<8><<<GATE_GRID, 128>>>(zp, b3, c2b, h1b, c1b, nullptr, nullptr);

    gemm64_kernel<2><<<dim3(32, 8), 256>>>(
        h1b, 0, W4, U4, 512, 128, G4H, zp, nullptr, nullptr, nullptr, nullptr);
    gates_kernel<8><<<GATE_GRID, 128>>>(
        zp, b4, c1b, h2b, c2b,
        out + (long long)Bsz * Vdim,
        out + (long long)Bsz * Vdim + Bsz * Hdim);

    // decoder: logits = h4 @ Wd (no split-K), grid 500x1, kc=512
    gemm64_kernel<0><<<dim3(Vdim / 64, 1), 256>>>(
        h2b, Hdim, Wd, nullptr, 1 << 30, 512, Vdim, lg,
        nullptr, nullptr, nullptr, nullptr);

    // softmax -> probs
    softmax_kernel<<<Bsz, 512>>>(lg, bd, out);
}

// round 5
// speedup vs baseline: 1.3158x; 1.3158x over previous
#include <cuda_runtime.h>

// ---------------------------------------------------------------------------
// Problem constants: B=64, S=20, E=512, H=512, V=32000, C=1000
//   D1 = 11264, virtual K1 = D1 + H = 11776, 4H = 2048
// ---------------------------------------------------------------------------
#define Bsz   64
#define Hdim  512
#define G4H   2048
#define Vdim  32000

// Scratch (device globals — allocation-free per harness rules)
static __device__ float g_zpart[16 * Bsz * G4H];   // 8.4 MB (max 16 split slices)
static __device__ float g_hbuf[2][Bsz * Hdim];
static __device__ float g_cbuf[2][Bsz * Hdim];
static __device__ float g_logits[Bsz * Vdim];      // 8.2 MB (single slice)

// ---------------------------------------------------------------------------
// f32x2 packed helpers (FFMA2: 2 fp32 MACs per issue)
// ---------------------------------------------------------------------------
__device__ __forceinline__ unsigned long long pack2(float lo, float hi) {
    unsigned long long r;
    asm("mov.b64 %0, {%1, %2};" : "=l"(r) : "f"(lo), "f"(hi));
    return r;
}
__device__ __forceinline__ void unpack2(unsigned long long v, float& lo, float& hi) {
    asm("mov.b64 {%0, %1}, %2;" : "=f"(lo), "=f"(hi) : "l"(v));
}
__device__ __forceinline__ void fma2(unsigned long long& d, unsigned long long a,
                                     unsigned long long b) {
    asm("fma.rn.f32x2 %0, %1, %2, %0;" : "+l"(d) : "l"(a), "l"(b));
}
__device__ __forceinline__ float sigmoidf_fast(float x) {
    return 1.0f / (1.0f + __expf(-x));
}

// ---------------------------------------------------------------------------
// Split-K partial GEMM, M=64 (batch), TILE_N=64, BK=16, 128 threads.
//   Zp[sp][m][n0+n] = sum_{k in [sp*kc,(sp+1)*kc)} Xv[m][k] * Wv[k][n0+n]
// Virtual X per MODE:
//   0: plain X (row stride ldx)                           (decoder)
//   1: [enc 10240 | word 512 | persona[spk] 512 | h0 512] (layer 1)
//   2: [h | h]  (col & 511)                               (layers 2-4)
// Virtual W: row < wsplit -> Wa[row], else Wb[row-wsplit]; both row-major, ld N.
// Micro-tile: 8 rows x 4 cols per thread. X kept as natural row-layout in smem
// (warp-broadcast LDS), W duplicated into f32x2 via pack MOVs.
// Inner loop: 3 x LDS.128 + 4 MOV + 16 FFMA2 per k.
// ---------------------------------------------------------------------------
template<int MODE>
__global__ __launch_bounds__(128, 6) void gemm64_kernel(
    const float* __restrict__ X, int ldx,
    const float* __restrict__ Wa, const float* __restrict__ Wb, int wsplit,
    int kc, int N, float* __restrict__ Zp,
    const float* __restrict__ enc, const float* __restrict__ word,
    const float* __restrict__ persona, const int* __restrict__ speaker)
{
    __shared__ __align__(16) float Xs[2][16][64];
    __shared__ __align__(16) float Ws[2][16][64];

    const int tid = threadIdx.x;
    const int tx = tid & 15;            // col group: cols tx*4 .. +3
    const int ty = tid >> 4;            // row group: rows ty*8 .. +7
    const int n0 = blockIdx.x * 64;
    const int sp = blockIdx.y;
    const int k0 = sp * kc;

    // ---- X loader: thread -> (row xr, k sub-offset xq in {0,8}) ----
    const int xr = tid & 63;
    const int xq = (tid >> 6) * 8;

    const float *encp = nullptr, *wordp = nullptr, *persp = nullptr, *h0p = nullptr;
    const float *xbase = nullptr;
    if (MODE == 1) {
        int spk = speaker[xr];
        encp  = enc + (long long)xr * 10240;
        wordp = word + (long long)xr * 512 - 10240;
        persp = persona + (long long)spk * 512 - 10752;
        h0p   = X + (long long)xr * 512 - 11264;   // X carries h0 in MODE 1
    } else if (MODE == 2) {
        xbase = X + (long long)xr * 512;
    } else {
        xbase = X + (long long)xr * ldx;
    }

    // loads BOTH float4s of this thread's 8-float window (never straddles a
    // segment boundary: boundaries are multiples of 16, windows 8-aligned)
    auto load_x = [&](int t, float4& a, float4& b) {
        int kg = k0 + t * 16 + xq;
        const float* p;
        if (MODE == 1) {
            p = (kg < 10240) ? (encp + kg)
              : (kg < 10752) ? (wordp + kg)
              : (kg < 11264) ? (persp + kg)
                             : (h0p + kg);
        } else if (MODE == 2) {
            p = xbase + (kg & 511);
        } else {
            p = xbase + kg;
        }
        a = *reinterpret_cast<const float4*>(p);
        b = *reinterpret_cast<const float4*>(p + 4);
    };

    // ---- W loader: wrow = tid>>3 (0..15), wcol = (tid&7)*8 ----
    const int wrow = tid >> 3;
    const int wcol = (tid & 7) * 8;
    auto load_w = [&](int t, float4& a, float4& b) {
        int r = k0 + t * 16 + wrow;
        const float* p = (r < wsplit)
            ? (Wa + (long long)r * N)
            : (Wb + (long long)(r - wsplit) * N);
        a = *reinterpret_cast<const float4*>(p + n0 + wcol);
        b = *reinterpret_cast<const float4*>(p + n0 + wcol + 4);
    };

    // preload tile 0
    float4 pxa, pxb, pwa, pwb;
    load_x(0, pxa, pxb);
    load_w(0, pwa, pwb);
    // store X transposed [k][m]
    Xs[0][xq + 0][xr] = pxa.x;  Xs[0][xq + 1][xr] = pxa.y;
    Xs[0][xq + 2][xr] = pxa.z;  Xs[0][xq + 3][xr] = pxa.w;
    Xs[0][xq + 4][xr] = pxb.x;  Xs[0][xq + 5][xr] = pxb.y;
    Xs[0][xq + 6][xr] = pxb.z;  Xs[0][xq + 7][xr] = pxb.w;
    *reinterpret_cast<float4*>(&Ws[0][wrow][wcol])     = pwa;
    *reinterpret_cast<float4*>(&Ws[0][wrow][wcol + 4]) = pwb;
    __syncthreads();

    unsigned long long acc[4][4];
#pragma unroll
    for (int i = 0; i < 4; i++)
#pragma unroll
        for (int j = 0; j < 4; j++) acc[i][j] = 0ULL;

    const int ntiles = kc >> 4;
    int buf = 0;
    for (int t = 0; t < ntiles; t++) {
        const bool has_next = (t + 1 < ntiles);
        if (has_next) {
            load_x(t + 1, pxa, pxb);
            load_w(t + 1, pwa, pwb);
        }
#pragma unroll
        for (int kk = 0; kk < 16; kk++) {
            ulonglong2 xa = *reinterpret_cast<const ulonglong2*>(&Xs[buf][kk][ty * 8]);
            ulonglong2 xb = *reinterpret_cast<const ulonglong2*>(&Xs[buf][kk][ty * 8 + 4]);
            float4 wv = *reinterpret_cast<const float4*>(&Ws[buf][kk][tx * 4]);
            unsigned long long w0 = pack2(wv.x, wv.x);
            unsigned long long w1 = pack2(wv.y, wv.y);
            unsigned long long w2 = pack2(wv.z, wv.z);
            unsigned long long w3 = pack2(wv.w, wv.w);
            fma2(acc[0][0], xa.x, w0); fma2(acc[0][1], xa.x, w1);
            fma2(acc[0][2], xa.x, w2); fma2(acc[0][3], xa.x, w3);
            fma2(acc[1][0], xa.y, w0); fma2(acc[1][1], xa.y, w1);
            fma2(acc[1][2], xa.y, w2); fma2(acc[1][3], xa.y, w3);
            fma2(acc[2][0], xb.x, w0); fma2(acc[2][1], xb.x, w1);
            fma2(acc[2][2], xb.x, w2); fma2(acc[2][3], xb.x, w3);
            fma2(acc[3][0], xb.y, w0); fma2(acc[3][1], xb.y, w1);
            fma2(acc[3][2], xb.y, w2); fma2(acc[3][3], xb.y, w3);
        }
        __syncthreads();
        if (has_next) {
            int nb = buf ^ 1;
            Xs[nb][xq + 0][xr] = pxa.x;  Xs[nb][xq + 1][xr] = pxa.y;
            Xs[nb][xq + 2][xr] = pxa.z;  Xs[nb][xq + 3][xr] = pxa.w;
            Xs[nb][xq + 4][xr] = pxb.x;  Xs[nb][xq + 5][xr] = pxb.y;
            Xs[nb][xq + 6][xr] = pxb.z;  Xs[nb][xq + 7][xr] = pxb.w;
            *reinterpret_cast<float4*>(&Ws[nb][wrow][wcol])     = pwa;
            *reinterpret_cast<float4*>(&Ws[nb][wrow][wcol + 4]) = pwb;
            buf = nb;
            __syncthreads();
        }
    }

    // epilogue: acc[rp][c] = rows (ty*8+2rp, ty*8+2rp+1), col tx*4+c
    float* zbase = Zp + ((long long)sp * 64 + ty * 8) * N + n0 + tx * 4;
#pragma unroll
    for (int rp = 0; rp < 4; rp++) {
        float lo[4], hi[4];
#pragma unroll
        for (int c = 0; c < 4; c++) unpack2(acc[rp][c], lo[c], hi[c]);
        *reinterpret_cast<float4*>(zbase + (long long)(2 * rp) * N) =
            make_float4(lo[0], lo[1], lo[2], lo[3]);
        *reinterpret_cast<float4*>(zbase + (long long)(2 * rp + 1) * N) =
            make_float4(hi[0], hi[1], hi[2], hi[3]);
    }
}

// ---------------------------------------------------------------------------
// Gate kernel (float2-vectorized): reduce NSL split slices + bias, apply
// Keras LSTM cell (gates i,f,g,o; act=relu, rec_act=sigmoid).
// ---------------------------------------------------------------------------
template<int NSL>
__global__ void gates_kernel(const float* __restrict__ Zp,
                             const float* __restrict__ bias,
                             const float* __restrict__ c_prev,
                             float* __restrict__ h_new,
                             float* __restrict__ c_new,
                             float* __restrict__ h_mir,
                             float* __restrict__ c_mir)
{
    int p2 = blockIdx.x * 128 + threadIdx.x;    // pair index < 64*256
    if (p2 >= Bsz * (Hdim / 2)) return;
    int bt = p2 >> 8;
    int j = (p2 & 255) * 2;

    float2 zi = *reinterpret_cast<const float2*>(bias + j);
    float2 zf = *reinterpret_cast<const float2*>(bias + 512 + j);
    float2 zg = *reinterpret_cast<const float2*>(bias + 1024 + j);
    float2 zo = *reinterpret_cast<const float2*>(bias + 1536 + j);
    const float* p = Zp + (long long)bt * G4H + j;
#pragma unroll
    for (int s = 0; s < NSL; s++) {
        const float* q = p + (long long)s * Bsz * G4H;
        float2 a = *reinterpret_cast<const float2*>(q);
        float2 b = *reinterpret_cast<const float2*>(q + 512);
        float2 c = *reinterpret_cast<const float2*>(q + 1024);
        float2 d = *reinterpret_cast<const float2*>(q + 1536);
        zi.x += a.x; zi.y += a.y;
        zf.x += b.x; zf.y += b.y;
        zg.x += c.x; zg.y += c.y;
        zo.x += d.x; zo.y += d.y;
    }
    int idx = bt * Hdim + j;
    float2 cp = *reinterpret_cast<const float2*>(c_prev + idx);
    float2 cv, hv;
    cv.x = sigmoidf_fast(zf.x) * cp.x + sigmoidf_fast(zi.x) * fmaxf(zg.x, 0.0f);
    cv.y = sigmoidf_fast(zf.y) * cp.y + sigmoidf_fast(zi.y) * fmaxf(zg.y, 0.0f);
    hv.x = sigmoidf_fast(zo.x) * fmaxf(cv.x, 0.0f);
    hv.y = sigmoidf_fast(zo.y) * fmaxf(cv.y, 0.0f);
    *reinterpret_cast<float2*>(c_new + idx) = cv;
    *reinterpret_cast<float2*>(h_new + idx) = hv;
    if (h_mir) {
        *reinterpret_cast<float2*>(h_mir + idx) = hv;
        *reinterpret_cast<float2*>(c_mir + idx) = cv;
    }
}

// ---------------------------------------------------------------------------
// Softmax over V=32000 per batch row (single logits slice + bias).
// ---------------------------------------------------------------------------
__global__ void softmax_kernel(const float* __restrict__ L,
                               const float* __restrict__ bd,
                               float* __restrict__ out)
{
    const int V = Vdim;
    int b = blockIdx.x;
    int tid = threadIdx.x;
    const float* r0 = L + (long long)b * V;

    float m = -1e30f, s = 0.0f;
    for (int v = tid; v < V; v += 512) {
        float val = r0[v] + bd[v];
        float nm = fmaxf(m, val);
        s = s * __expf(m - nm) + __expf(val - nm);
        m = nm;
    }
    __shared__ float sm[512], ss[512];
    sm[tid] = m;
    ss[tid] = s;
    __syncthreads();
    for (int st = 256; st > 0; st >>= 1) {
        if (tid < st) {
            float m2 = sm[tid + st], s2 = ss[tid + st];
            float nm = fmaxf(sm[tid], m2);
            ss[tid] = ss[tid] * __expf(sm[tid] - nm) + s2 * __expf(m2 - nm);
            sm[tid] = nm;
        }
        __syncthreads();
    }
    float M = sm[0];
    float Sinv = 1.0f / ss[0];
    for (int v = tid; v < V; v += 512) {
        float val = r0[v] + bd[v];
        out[(long long)b * V + v] = __expf(val - M) * Sinv;
    }
}

// ---------------------------------------------------------------------------
// kernel_launch
// ---------------------------------------------------------------------------
extern "C" void kernel_launch(void* const* d_in, const int* in_sizes, int n_in,
                              void* d_out, int out_size)
{
    const float* enc     = (const float*)d_in[0];
    const float* word    = (const float*)d_in[1];
    const float* h0      = (const float*)d_in[2];
    const float* c0      = (const float*)d_in[3];
    const float* persona = (const float*)d_in[4];
    const float* W1      = (const float*)d_in[5];
    const float* U1      = (const float*)d_in[6];
    const float* b1      = (const float*)d_in[7];
    const float* W2      = (const float*)d_in[8];
    const float* U2      = (const float*)d_in[9];
    const float* b2      = (const float*)d_in[10];
    const float* W3      = (const float*)d_in[11];
    const float* U3      = (const float*)d_in[12];
    const float* b3      = (const float*)d_in[13];
    const float* W4      = (const float*)d_in[14];
    const float* U4      = (const float*)d_in[15];
    const float* b4      = (const float*)d_in[16];
    const float* Wd      = (const float*)d_in[17];
    const float* bd      = (const float*)d_in[18];
    const int*   speaker = (const int*)d_in[19];
    float* out = (float*)d_out;

    void *pz, *ph, *pc, *pl;
    cudaGetSymbolAddress(&pz, g_zpart);
    cudaGetSymbolAddress(&ph, g_hbuf);
    cudaGetSymbolAddress(&pc, g_cbuf);
    cudaGetSymbolAddress(&pl, g_logits);
    float* zp = (float*)pz;
    float* hb = (float*)ph;
    float* cb = (float*)pc;
    float* lg = (float*)pl;
    float* h1b = hb;
    float* h2b = hb + Bsz * Hdim;
    float* c1b = cb;
    float* c2b = cb + Bsz * Hdim;

    const int GATE_GRID = (Bsz * Hdim / 2) / 128;   // 128 blocks of 128

    // layer 1: z = [x|h0] @ [W1;U1], K=11776, 16 splits of 736, grid 32x16=512
    gemm64_kernel<1><<<dim3(32, 16), 128>>>(
        h0, 0, W1, U1, 11264, 736, G4H, zp, enc, word, persona, speaker);
    gates_kernel<16><<<GATE_GRID, 128>>>(zp, b1, c0, h1b, c1b, nullptr, nullptr);

    // layers 2..4: z = [h|h] @ [W;U], K=1024, 8 splits of 128, grid 32x8=256
    gemm64_kernel<2><<<dim3(32, 8), 128>>>(
        h1b, 0, W2, U2, 512, 128, G4H, zp, nullptr, nullptr, nullptr, nullptr);
    gates_kernel<8><<<GATE_GRID, 128>>>(zp, b2, c1b, h2b, c2b, nullptr, nullptr);

    gemm64_kernel<2><<<dim3(32, 8), 128>>>(
        h2b, 0, W3, U3, 512, 128, G4H, zp, nullptr, nullptr, nullptr, nullptr);
    gates_kernel<8><<<GATE_GRID, 128>>>(zp, b3, c2b, h1b, c1b, nullptr, nullptr);

    gemm64_kernel<2><<<dim3(32, 8), 128>>>(
        h1b, 0, W4, U4, 512, 128, G4H, zp, nullptr, nullptr, nullptr, nullptr);
    gates_kernel<8><<<GATE_GRID, 128>>>(
        zp, b4, c1b, h2b, c2b,
        out + (long long)Bsz * Vdim,
        out + (long long)Bsz * Vdim + Bsz * Hdim);

    // decoder: logits = h4 @ Wd, no split-K, grid 500
    gemm64_kernel<0><<<dim3(Vdim / 64, 1), 128>>>(
        h2b, Hdim, Wd, Wd, 1 << 30, 512, Vdim, lg,
        nullptr, nullptr, nullptr, nullptr);

    // softmax -> probs
    softmax_kernel<<<Bsz, 512>>>(lg, bd, out);
}

// round 7
// speedup vs baseline: 1.4921x; 1.1339x over previous
#include <cuda_runtime.h>
#include <cuda_bf16.h>
#include <cstdint>

// ---------------------------------------------------------------------------
// Problem constants: B=64, S=20, E=512, H=512, V=32000, C=1000
//   D1 = 11264, virtual K1 = 11776 = [enc|word|persona|h0], 4H = 2048
// ---------------------------------------------------------------------------
#define Bsz   64
#define Hdim  512
#define G4H   2048
#define Vdim  32000

static __device__ float g_zpart[8 * Bsz * G4H];    // 4.2 MB (8 split slices)
static __device__ float g_hbuf[2][Bsz * Hdim];
static __device__ float g_cbuf[2][Bsz * Hdim];
static __device__ float g_logits[Bsz * Vdim];      // 8.2 MB

__device__ __forceinline__ float sigmoidf_fast(float x) {
    return 1.0f / (1.0f + __expf(-x));
}
__device__ __forceinline__ uint32_t smem_u32(const void* p) {
    uint32_t a;
    asm("{ .reg .u64 t; cvta.to.shared.u64 t, %1; cvt.u32.u64 %0, t; }"
        : "=r"(a) : "l"(p));
    return a;
}
__device__ __forceinline__ uint32_t bfpack(__nv_bfloat16 a, __nv_bfloat16 b) {
    return (uint32_t)__bfloat16_as_ushort(a) | ((uint32_t)__bfloat16_as_ushort(b) << 16);
}
__device__ __forceinline__ void ldsm4(uint32_t* r, uint32_t addr) {
    asm volatile("ldmatrix.sync.aligned.m8n8.x4.shared.b16 {%0,%1,%2,%3}, [%4];"
                 : "=r"(r[0]), "=r"(r[1]), "=r"(r[2]), "=r"(r[3]) : "r"(addr));
}
__device__ __forceinline__ void ldsm4t(uint32_t* r, uint32_t addr) {
    asm volatile("ldmatrix.sync.aligned.m8n8.x4.trans.shared.b16 {%0,%1,%2,%3}, [%4];"
                 : "=r"(r[0]), "=r"(r[1]), "=r"(r[2]), "=r"(r[3]) : "r"(addr));
}
__device__ __forceinline__ void mma16816(float* d, const uint32_t* a,
                                         uint32_t b0, uint32_t b1) {
    asm volatile(
        "mma.sync.aligned.m16n8k16.row.col.f32.bf16.bf16.f32 "
        "{%0,%1,%2,%3}, {%4,%5,%6,%7}, {%8,%9}, {%0,%1,%2,%3};"
        : "+f"(d[0]), "+f"(d[1]), "+f"(d[2]), "+f"(d[3])
        : "r"(a[0]), "r"(a[1]), "r"(a[2]), "r"(a[3]), "r"(b0), "r"(b1));
}

// ---------------------------------------------------------------------------
// bf16 Dekker-split warp-MMA GEMM.  M=64 (batch), TILE_N=64, BK=32, 128 thr.
//   Z[sp][m][n0+n] = sum_{k in [sp*kc,(sp+1)*kc)} Xv[m][k] * Wv[k][n]
// Each fp32 x splits exactly as bf16 hi+lo; z accumulates 3 Dekker streams
// (xh*wh + xh*wl + xl*wh) into ONE fp32 accumulator set (err ~2^-17).
// Virtual X per MODE:
//   0: plain X (row stride ldx)                           (decoder)
//   1: [enc 10240 | word 512 | persona[spk] 512 | h0 512] (layer 1)
//   2: [h | h]  (col & 511)                               (layers 2-4)
// Virtual W: row < wsplit -> Wa[row] else Wb[row-wsplit]; row-major, ld N.
// Per warp: 64(M) x 16(N) strip = 4 Mtiles x 2 Ntiles of m16n8k16.
// ---------------------------------------------------------------------------
template<int MODE>
__global__ __launch_bounds__(128, 3) void mma_gemm_kernel(
    const float* __restrict__ X, int ldx,
    const float* __restrict__ Wa, const float* __restrict__ Wb, int wsplit,
    int kc, int N, float* __restrict__ Zall,
    const float* __restrict__ enc, const float* __restrict__ word,
    const float* __restrict__ persona, const int* __restrict__ speaker)
{
    __shared__ __align__(16) __nv_bfloat16 Ah[2][64][40];  // stride 80B: LDSM conflict-free
    __shared__ __align__(16) __nv_bfloat16 Al[2][64][40];
    __shared__ __align__(16) __nv_bfloat16 Bh[2][32][72];  // stride 144B: conflict-free
    __shared__ __align__(16) __nv_bfloat16 Bl[2][32][72];

    const int tid = threadIdx.x;
    const int lane = tid & 31;
    const int warp = tid >> 5;
    const int n0 = blockIdx.x * 64;
    const int sp = blockIdx.y;
    const int k0 = sp * kc;
    float* Z = Zall + (long long)sp * 64 * N;

    // ---- A loader mapping: row xm (0..63), k window start xh2 in {0,16} ----
    const int xm = tid >> 1;
    const int xh2 = (tid & 1) * 16;
    const float *xa = nullptr, *xb = nullptr, *xc = nullptr, *xd = nullptr, *xp = nullptr;
    if (MODE == 1) {
        int spk = speaker[xm];
        xa = enc + (long long)xm * 10240;
        xb = word + (long long)xm * 512 - 10240;
        xc = persona + (long long)spk * 512 - 10752;
        xd = X + (long long)xm * 512 - 11264;      // X carries h0 in MODE 1
    } else if (MODE == 2) {
        xp = X + (long long)xm * 512;
    } else {
        xp = X + (long long)xm * ldx;
    }
    // ---- B loader mapping: k-row bk (0..31), n segment bn in {0,16,32,48} ----
    const int bk = tid >> 2;
    const int bn = (tid & 3) * 16;

    float4 ar[4], br[4];
    auto loadA = [&](int t) {
        int kg = k0 + t * 32 + xh2;          // 16-aligned; segments 16-aligned
        const float* p;
        if (MODE == 1)
            p = (kg < 10240) ? (xa + kg) : (kg < 10752) ? (xb + kg)
              : (kg < 11264) ? (xc + kg) : (xd + kg);
        else if (MODE == 2)
            p = xp + (kg & 511);
        else
            p = xp + kg;
#pragma unroll
        for (int i = 0; i < 4; i++) ar[i] = *reinterpret_cast<const float4*>(p + i * 4);
    };
    auto loadB = [&](int t) {
        int r = k0 + t * 32 + bk;
        const float* p = (r < wsplit) ? (Wa + (long long)r * N)
                                      : (Wb + (long long)(r - wsplit) * N);
#pragma unroll
        for (int i = 0; i < 4; i++)
            br[i] = *reinterpret_cast<const float4*>(p + n0 + bn + i * 4);
    };
    auto storeA = [&](int b) {
#pragma unroll
        for (int i = 0; i < 4; i++) {
            float4 v = ar[i];
            __nv_bfloat16 h0 = __float2bfloat16(v.x), h1 = __float2bfloat16(v.y);
            __nv_bfloat16 h2 = __float2bfloat16(v.z), h3 = __float2bfloat16(v.w);
            __nv_bfloat16 l0 = __float2bfloat16(v.x - __bfloat162float(h0));
            __nv_bfloat16 l1 = __float2bfloat16(v.y - __bfloat162float(h1));
            __nv_bfloat16 l2 = __float2bfloat16(v.z - __bfloat162float(h2));
            __nv_bfloat16 l3 = __float2bfloat16(v.w - __bfloat162float(h3));
            *reinterpret_cast<uint2*>(&Ah[b][xm][xh2 + i * 4]) =
                make_uint2(bfpack(h0, h1), bfpack(h2, h3));
            *reinterpret_cast<uint2*>(&Al[b][xm][xh2 + i * 4]) =
                make_uint2(bfpack(l0, l1), bfpack(l2, l3));
        }
    };
    auto storeB = [&](int b) {
#pragma unroll
        for (int i = 0; i < 4; i++) {
            float4 v = br[i];
            __nv_bfloat16 h0 = __float2bfloat16(v.x), h1 = __float2bfloat16(v.y);
            __nv_bfloat16 h2 = __float2bfloat16(v.z), h3 = __float2bfloat16(v.w);
            __nv_bfloat16 l0 = __float2bfloat16(v.x - __bfloat162float(h0));
            __nv_bfloat16 l1 = __float2bfloat16(v.y - __bfloat162float(h1));
            __nv_bfloat16 l2 = __float2bfloat16(v.z - __bfloat162float(h2));
            __nv_bfloat16 l3 = __float2bfloat16(v.w - __bfloat162float(h3));
            *reinterpret_cast<uint2*>(&Bh[b][bk][bn + i * 4]) =
                make_uint2(bfpack(h0, h1), bfpack(h2, h3));
            *reinterpret_cast<uint2*>(&Bl[b][bk][bn + i * 4]) =
                make_uint2(bfpack(l0, l1), bfpack(l2, l3));
        }
    };

    float acc[4][2][4];
#pragma unroll
    for (int mt = 0; mt < 4; mt++)
#pragma unroll
        for (int nt = 0; nt < 2; nt++)
#pragma unroll
            for (int e = 0; e < 4; e++) acc[mt][nt][e] = 0.0f;

    const int NT = kc >> 5;     // BK = 32
    loadA(0); loadB(0);
    storeA(0); storeB(0);
    __syncthreads();

    const int nw = warp * 16;
    const int lr = lane & 15;           // ldmatrix row within 16
    const int lc = (lane >> 4) * 8;     // ldmatrix col-half select

    for (int t = 0; t < NT; t++) {
        const int buf = t & 1;
        const bool has_next = (t + 1 < NT);
        if (has_next) { loadA(t + 1); loadB(t + 1); }

#pragma unroll
        for (int s = 0; s < 2; s++) {
            uint32_t bhf[4], blf[4];
            ldsm4t(bhf, smem_u32(&Bh[buf][s * 16 + lr][nw + lc]));
            ldsm4t(blf, smem_u32(&Bl[buf][s * 16 + lr][nw + lc]));
#pragma unroll
            for (int mt = 0; mt < 4; mt++) {
                uint32_t ahf[4], alf[4];
                ldsm4(ahf, smem_u32(&Ah[buf][mt * 16 + lr][s * 16 + lc]));
                ldsm4(alf, smem_u32(&Al[buf][mt * 16 + lr][s * 16 + lc]));
                mma16816(acc[mt][0], ahf, bhf[0], bhf[1]);
                mma16816(acc[mt][1], ahf, bhf[2], bhf[3]);
                mma16816(acc[mt][0], ahf, blf[0], blf[1]);
                mma16816(acc[mt][1], ahf, blf[2], blf[3]);
                mma16816(acc[mt][0], alf, bhf[0], bhf[1]);
                mma16816(acc[mt][1], alf, bhf[2], bhf[3]);
            }
        }
        if (has_next) { storeA((t + 1) & 1); storeB((t + 1) & 1); }
        __syncthreads();
    }

    // epilogue: thread holds rows (mt*16 + lane/4, +8), cols nt*8 + (lane%4)*2
#pragma unroll
    for (int mt = 0; mt < 4; mt++)
#pragma unroll
        for (int nt = 0; nt < 2; nt++) {
            int row = mt * 16 + (lane >> 2);
            int col = n0 + nw + nt * 8 + (lane & 3) * 2;
            *reinterpret_cast<float2*>(&Z[(long long)row * N + col]) =
                make_float2(acc[mt][nt][0], acc[mt][nt][1]);
            *reinterpret_cast<float2*>(&Z[(long long)(row + 8) * N + col]) =
                make_float2(acc[mt][nt][2], acc[mt][nt][3]);
        }
}

// ---------------------------------------------------------------------------
// Gate kernel (float2): reduce NSL split slices + bias, Keras LSTM cell
//   (gates i,f,g,o; activation=relu, recurrent_activation=sigmoid)
// ---------------------------------------------------------------------------
template<int NSL>
__global__ void gates_kernel(const float* __restrict__ Zp,
                             const float* __restrict__ bias,
                             const float* __restrict__ c_prev,
                             float* __restrict__ h_new,
                             float* __restrict__ c_new,
                             float* __restrict__ h_mir,
                             float* __restrict__ c_mir)
{
    int p2 = blockIdx.x * 128 + threadIdx.x;
    if (p2 >= Bsz * (Hdim / 2)) return;
    int bt = p2 >> 8;
    int j = (p2 & 255) * 2;

    float2 zi = *reinterpret_cast<const float2*>(bias + j);
    float2 zf = *reinterpret_cast<const float2*>(bias + 512 + j);
    float2 zg = *reinterpret_cast<const float2*>(bias + 1024 + j);
    float2 zo = *reinterpret_cast<const float2*>(bias + 1536 + j);
    const float* p = Zp + (long long)bt * G4H + j;
#pragma unroll
    for (int s = 0; s < NSL; s++) {
        const float* q = p + (long long)s * Bsz * G4H;
        float2 a = *reinterpret_cast<const float2*>(q);
        float2 b = *reinterpret_cast<const float2*>(q + 512);
        float2 c = *reinterpret_cast<const float2*>(q + 1024);
        float2 d = *reinterpret_cast<const float2*>(q + 1536);
        zi.x += a.x; zi.y += a.y;
        zf.x += b.x; zf.y += b.y;
        zg.x += c.x; zg.y += c.y;
        zo.x += d.x; zo.y += d.y;
    }
    int idx = bt * Hdim + j;
    float2 cp = *reinterpret_cast<const float2*>(c_prev + idx);
    float2 cv, hv;
    cv.x = sigmoidf_fast(zf.x) * cp.x + sigmoidf_fast(zi.x) * fmaxf(zg.x, 0.0f);
    cv.y = sigmoidf_fast(zf.y) * cp.y + sigmoidf_fast(zi.y) * fmaxf(zg.y, 0.0f);
    hv.x = sigmoidf_fast(zo.x) * fmaxf(cv.x, 0.0f);
    hv.y = sigmoidf_fast(zo.y) * fmaxf(cv.y, 0.0f);
    *reinterpret_cast<float2*>(c_new + idx) = cv;
    *reinterpret_cast<float2*>(h_new + idx) = hv;
    if (h_mir) {
        *reinterpret_cast<float2*>(h_mir + idx) = hv;
        *reinterpret_cast<float2*>(c_mir + idx) = cv;
    }
}

// ---------------------------------------------------------------------------
// Softmax over V=32000 per batch row (single logits slice + bias)
// ---------------------------------------------------------------------------
__global__ void softmax_kernel(const float* __restrict__ L,
                               const float* __restrict__ bd,
                               float* __restrict__ out)
{
    const int V = Vdim;
    int b = blockIdx.x;
    int tid = threadIdx.x;
    const float* r0 = L + (long long)b * V;

    float m = -1e30f, s = 0.0f;
    for (int v = tid; v < V; v += 512) {
        float val = r0[v] + bd[v];
        float nm = fmaxf(m, val);
        s = s * __expf(m - nm) + __expf(val - nm);
        m = nm;
    }
    __shared__ float sm[512], ss[512];
    sm[tid] = m; ss[tid] = s;
    __syncthreads();
    for (int st = 256; st > 0; st >>= 1) {
        if (tid < st) {
            float m2 = sm[tid + st], s2 = ss[tid + st];
            float nm = fmaxf(sm[tid], m2);
            ss[tid] = ss[tid] * __expf(sm[tid] - nm) + s2 * __expf(m2 - nm);
            sm[tid] = nm;
        }
        __syncthreads();
    }
    float M = sm[0];
    float Sinv = 1.0f / ss[0];
    for (int v = tid; v < V; v += 512) {
        float val = r0[v] + bd[v];
        out[(long long)b * V + v] = __expf(val - M) * Sinv;
    }
}

// ---------------------------------------------------------------------------
// kernel_launch
// ---------------------------------------------------------------------------
extern "C" void kernel_launch(void* const* d_in, const int* in_sizes, int n_in,
                              void* d_out, int out_size)
{
    const float* enc     = (const float*)d_in[0];
    const float* word    = (const float*)d_in[1];
    const float* h0      = (const float*)d_in[2];
    const float* c0      = (const float*)d_in[3];
    const float* persona = (const float*)d_in[4];
    const float* W1      = (const float*)d_in[5];
    const float* U1      = (const float*)d_in[6];
    const float* b1      = (const float*)d_in[7];
    const float* W2      = (const float*)d_in[8];
    const float* U2      = (const float*)d_in[9];
    const float* b2      = (const float*)d_in[10];
    const float* W3      = (const float*)d_in[11];
    const float* U3      = (const float*)d_in[12];
    const float* b3      = (const float*)d_in[13];
    const float* W4      = (const float*)d_in[14];
    const float* U4      = (const float*)d_in[15];
    const float* b4      = (const float*)d_in[16];
    const float* Wd      = (const float*)d_in[17];
    const float* bd      = (const float*)d_in[18];
    const int*   speaker = (const int*)d_in[19];
    float* out = (float*)d_out;

    void *pz, *ph, *pc, *pl;
    cudaGetSymbolAddress(&pz, g_zpart);
    cudaGetSymbolAddress(&ph, g_hbuf);
    cudaGetSymbolAddress(&pc, g_cbuf);
    cudaGetSymbolAddress(&pl, g_logits);
    float* zp = (float*)pz;
    float* hb = (float*)ph;
    float* cb = (float*)pc;
    float* lg = (float*)pl;
    float* h1b = hb;
    float* h2b = hb + Bsz * Hdim;
    float* c1b = cb;
    float* c2b = cb + Bsz * Hdim;

    const int GATE_GRID = (Bsz * Hdim / 2) / 128;   // 128 blocks

    // layer 1: z = [x|h0] @ [W1;U1], K=11776, 8 splits of 1472, grid 32x8
    mma_gemm_kernel<1><<<dim3(32, 8), 128>>>(
        h0, 512, W1, U1, 11264, 1472, G4H, zp, enc, word, persona, speaker);
    gates_kernel<8><<<GATE_GRID, 128>>>(zp, b1, c0, h1b, c1b, nullptr, nullptr);

    // layers 2..4: z = [h|h] @ [W;U], K=1024, 2 splits of 512, grid 32x2
    mma_gemm_kernel<2><<<dim3(32, 2), 128>>>(
        h1b, 512, W2, U2, 512, 512, G4H, zp, nullptr, nullptr, nullptr, nullptr);
    gates_kernel<2><<<GATE_GRID, 128>>>(zp, b2, c1b, h2b, c2b, nullptr, nullptr);

    mma_gemm_kernel<2><<<dim3(32, 2), 128>>>(
        h2b, 512, W3, U3, 512, 512, G4H, zp, nullptr, nullptr, nullptr, nullptr);
    gates_kernel<2><<<GATE_GRID, 128>>>(zp, b3, c2b, h1b, c1b, nullptr, nullptr);

    mma_gemm_kernel<2><<<dim3(32, 2), 128>>>(
        h1b, 512, W4, U4, 512, 512, G4H, zp, nullptr, nullptr, nullptr, nullptr);
    gates_kernel<2><<<GATE_GRID, 128>>>(
        zp, b4, c1b, h2b, c2b,
        out + (long long)Bsz * Vdim,
        out + (long long)Bsz * Vdim + Bsz * Hdim);

    // decoder: logits = h4 @ Wd, grid 500, no split-K
    mma_gemm_kernel<0><<<dim3(500, 1), 128>>>(
        h2b, 512, Wd, Wd, 1 << 30, 512, Vdim, lg,
        nullptr, nullptr, nullptr, nullptr);

    // softmax -> probs
    softmax_kernel<<<Bsz, 512>>>(lg, bd, out);
}

// round 8
// speedup vs baseline: 1.6998x; 1.1392x over previous
#include <cuda_runtime.h>
#include <cuda_bf16.h>
#include <cstdint>

// ---------------------------------------------------------------------------
// Problem constants: B=64, S=20, E=512, H=512, V=32000, C=1000
//   D1 = 11264, virtual K1 = 11776 = [enc|word|persona|h0], 4H = 2048
// ---------------------------------------------------------------------------
#define Bsz   64
#define Hdim  512
#define G4H   2048
#define Vdim  32000

static __device__ float g_zpart[8 * Bsz * G4H];    // 4.2 MB (8 split slices)
static __device__ float g_hbuf[2][Bsz * Hdim];
static __device__ float g_cbuf[2][Bsz * Hdim];
static __device__ float g_logits[Bsz * Vdim];      // 8.2 MB

__device__ __forceinline__ float sigmoidf_fast(float x) {
    return 1.0f / (1.0f + __expf(-x));
}
__device__ __forceinline__ uint32_t smem_u32(const void* p) {
    uint32_t a;
    asm("{ .reg .u64 t; cvta.to.shared.u64 t, %1; cvt.u32.u64 %0, t; }"
        : "=r"(a) : "l"(p));
    return a;
}
__device__ __forceinline__ void ldsm4(uint32_t* r, uint32_t addr) {
    asm volatile("ldmatrix.sync.aligned.m8n8.x4.shared.b16 {%0,%1,%2,%3}, [%4];"
                 : "=r"(r[0]), "=r"(r[1]), "=r"(r[2]), "=r"(r[3]) : "r"(addr));
}
__device__ __forceinline__ void ldsm4t(uint32_t* r, uint32_t addr) {
    asm volatile("ldmatrix.sync.aligned.m8n8.x4.trans.shared.b16 {%0,%1,%2,%3}, [%4];"
                 : "=r"(r[0]), "=r"(r[1]), "=r"(r[2]), "=r"(r[3]) : "r"(addr));
}
__device__ __forceinline__ void mma16816(float* d, const uint32_t* a,
                                         uint32_t b0, uint32_t b1) {
    asm volatile(
        "mma.sync.aligned.m16n8k16.row.col.f32.bf16.bf16.f32 "
        "{%0,%1,%2,%3}, {%4,%5,%6,%7}, {%8,%9}, {%0,%1,%2,%3};"
        : "+f"(d[0]), "+f"(d[1]), "+f"(d[2]), "+f"(d[3])
        : "r"(a[0]), "r"(a[1]), "r"(a[2]), "r"(a[3]), "r"(b0), "r"(b1));
}
// Dekker split of 2 floats -> packed bf16x2 hi + packed bf16x2 lo.
// hi = rn(bf16(x)); lo = rn(bf16(x - float(hi))). Exactly matches
// __float2bfloat16 element-wise, but 1 CVT per 2 elements + packed output.
__device__ __forceinline__ void dek2(float x, float y, uint32_t& hp, uint32_t& lp) {
    asm("cvt.rn.bf16x2.f32 %0, %1, %2;" : "=r"(hp) : "f"(y), "f"(x));
    float fx = __uint_as_float(hp << 16);
    float fy = __uint_as_float(hp & 0xFFFF0000u);
    asm("cvt.rn.bf16x2.f32 %0, %1, %2;" : "=r"(lp) : "f"(y - fy), "f"(x - fx));
}

// diagnostic spacer: shifts the interesting GEMM into ncu's -s 5 -c 1 window
__global__ void noop_kernel() {}

// ---------------------------------------------------------------------------
// bf16 Dekker-split warp-MMA GEMM.  M=64 (batch), TILE_N=64, BK=32, 128 thr.
//   Z[sp][m][n0+n] = sum_{k in [sp*kc,(sp+1)*kc)} Xv[m][k] * Wv[k][n]
// 3 Dekker streams (xh*wh + xh*wl + xl*wh) into ONE fp32 accumulator set.
// Virtual X per MODE:
//   0: plain X (row stride ldx)                           (decoder)
//   1: [enc 10240 | word 512 | persona[spk] 512 | h0 512] (layer 1)
//   2: [h | h]  (col & 511)                               (layers 2-4)
// Virtual W: row < wsplit -> Wa[row] else Wb[row-wsplit]; row-major, ld N.
// Per warp: 64(M) x 16(N) strip = 4 Mtiles x 2 Ntiles of m16n8k16.
// ---------------------------------------------------------------------------
template<int MODE>
__global__ __launch_bounds__(128, 3) void mma_gemm_kernel(
    const float* __restrict__ X, int ldx,
    const float* __restrict__ Wa, const float* __restrict__ Wb, int wsplit,
    int kc, int N, float* __restrict__ Zall,
    const float* __restrict__ enc, const float* __restrict__ word,
    const float* __restrict__ persona, const int* __restrict__ speaker)
{
    __shared__ __align__(16) __nv_bfloat16 Ah[2][64][40];  // stride 80B: LDSM conflict-free
    __shared__ __align__(16) __nv_bfloat16 Al[2][64][40];
    __shared__ __align__(16) __nv_bfloat16 Bh[2][32][72];  // stride 144B: conflict-free
    __shared__ __align__(16) __nv_bfloat16 Bl[2][32][72];

    const int tid = threadIdx.x;
    const int lane = tid & 31;
    const int warp = tid >> 5;
    const int n0 = blockIdx.x * 64;
    const int sp = blockIdx.y;
    const int k0 = sp * kc;
    float* Z = Zall + (long long)sp * 64 * N;

    // ---- A loader mapping: row xm (0..63), k window start xh2 in {0,16} ----
    const int xm = tid >> 1;
    const int xh2 = (tid & 1) * 16;
    const float *xa = nullptr, *xb = nullptr, *xc = nullptr, *xd = nullptr, *xp = nullptr;
    if (MODE == 1) {
        int spk = speaker[xm];
        xa = enc + (long long)xm * 10240;
        xb = word + (long long)xm * 512 - 10240;
        xc = persona + (long long)spk * 512 - 10752;
        xd = X + (long long)xm * 512 - 11264;      // X carries h0 in MODE 1
    } else if (MODE == 2) {
        xp = X + (long long)xm * 512;
    } else {
        xp = X + (long long)xm * ldx;
    }
    // ---- B loader mapping: k-row bk (0..31), n segment bn in {0,16,32,48} ----
    const int bk = tid >> 2;
    const int bn = (tid & 3) * 16;

    float4 ar[4], br[4];
    auto loadA = [&](int t) {
        int kg = k0 + t * 32 + xh2;          // 16-aligned; segments 16-aligned
        const float* p;
        if (MODE == 1)
            p = (kg < 10240) ? (xa + kg) : (kg < 10752) ? (xb + kg)
              : (kg < 11264) ? (xc + kg) : (xd + kg);
        else if (MODE == 2)
            p = xp + (kg & 511);
        else
            p = xp + kg;
#pragma unroll
        for (int i = 0; i < 4; i++) ar[i] = *reinterpret_cast<const float4*>(p + i * 4);
    };
    auto loadB = [&](int t) {
        int r = k0 + t * 32 + bk;
        const float* p = (r < wsplit) ? (Wa + (long long)r * N)
                                      : (Wb + (long long)(r - wsplit) * N);
#pragma unroll
        for (int i = 0; i < 4; i++)
            br[i] = *reinterpret_cast<const float4*>(p + n0 + bn + i * 4);
    };
    auto storeA = [&](int b) {
#pragma unroll
        for (int i = 0; i < 4; i++) {
            float4 v = ar[i];
            uint32_t h01, l01, h23, l23;
            dek2(v.x, v.y, h01, l01);
            dek2(v.z, v.w, h23, l23);
            *reinterpret_cast<uint2*>(&Ah[b][xm][xh2 + i * 4]) = make_uint2(h01, h23);
            *reinterpret_cast<uint2*>(&Al[b][xm][xh2 + i * 4]) = make_uint2(l01, l23);
        }
    };
    auto storeB = [&](int b) {
#pragma unroll
        for (int i = 0; i < 4; i++) {
            float4 v = br[i];
            uint32_t h01, l01, h23, l23;
            dek2(v.x, v.y, h01, l01);
            dek2(v.z, v.w, h23, l23);
            *reinterpret_cast<uint2*>(&Bh[b][bk][bn + i * 4]) = make_uint2(h01, h23);
            *reinterpret_cast<uint2*>(&Bl[b][bk][bn + i * 4]) = make_uint2(l01, l23);
        }
    };

    float acc[4][2][4];
#pragma unroll
    for (int mt = 0; mt < 4; mt++)
#pragma unroll
        for (int nt = 0; nt < 2; nt++)
#pragma unroll
            for (int e = 0; e < 4; e++) acc[mt][nt][e] = 0.0f;

    const int NT = kc >> 5;     // BK = 32
    loadA(0); loadB(0);
    storeA(0); storeB(0);
    __syncthreads();

    const int nw = warp * 16;
    const int lr = lane & 15;           // ldmatrix row within 16
    const int lc = (lane >> 4) * 8;     // ldmatrix col-half select

    for (int t = 0; t < NT; t++) {
        const int buf = t & 1;
        const bool has_next = (t + 1 < NT);
        if (has_next) { loadA(t + 1); loadB(t + 1); }

#pragma unroll
        for (int s = 0; s < 2; s++) {
            uint32_t bhf[4], blf[4];
            ldsm4t(bhf, smem_u32(&Bh[buf][s * 16 + lr][nw + lc]));
            ldsm4t(blf, smem_u32(&Bl[buf][s * 16 + lr][nw + lc]));
#pragma unroll
            for (int mt = 0; mt < 4; mt++) {
                uint32_t ahf[4], alf[4];
                ldsm4(ahf, smem_u32(&Ah[buf][mt * 16 + lr][s * 16 + lc]));
                ldsm4(alf, smem_u32(&Al[buf][mt * 16 + lr][s * 16 + lc]));
                mma16816(acc[mt][0], ahf, bhf[0], bhf[1]);
                mma16816(acc[mt][1], ahf, bhf[2], bhf[3]);
                mma16816(acc[mt][0], ahf, blf[0], blf[1]);
                mma16816(acc[mt][1], ahf, blf[2], blf[3]);
                mma16816(acc[mt][0], alf, bhf[0], bhf[1]);
                mma16816(acc[mt][1], alf, bhf[2], bhf[3]);
            }
        }
        if (has_next) { storeA((t + 1) & 1); storeB((t + 1) & 1); }
        __syncthreads();
    }

    // epilogue: thread holds rows (mt*16 + lane/4, +8), cols nt*8 + (lane%4)*2
#pragma unroll
    for (int mt = 0; mt < 4; mt++)
#pragma unroll
        for (int nt = 0; nt < 2; nt++) {
            int row = mt * 16 + (lane >> 2);
            int col = n0 + nw + nt * 8 + (lane & 3) * 2;
            *reinterpret_cast<float2*>(&Z[(long long)row * N + col]) =
                make_float2(acc[mt][nt][0], acc[mt][nt][1]);
            *reinterpret_cast<float2*>(&Z[(long long)(row + 8) * N + col]) =
                make_float2(acc[mt][nt][2], acc[mt][nt][3]);
        }
}

// ---------------------------------------------------------------------------
// Gate kernel (float2): reduce NSL split slices + bias, Keras LSTM cell
//   (gates i,f,g,o; activation=relu, recurrent_activation=sigmoid)
// ---------------------------------------------------------------------------
template<int NSL>
__global__ void gates_kernel(const float* __restrict__ Zp,
                             const float* __restrict__ bias,
                             const float* __restrict__ c_prev,
                             float* __restrict__ h_new,
                             float* __restrict__ c_new,
                             float* __restrict__ h_mir,
                             float* __restrict__ c_mir)
{
    int p2 = blockIdx.x * 128 + threadIdx.x;
    if (p2 >= Bsz * (Hdim / 2)) return;
    int bt = p2 >> 8;
    int j = (p2 & 255) * 2;

    float2 zi = *reinterpret_cast<const float2*>(bias + j);
    float2 zf = *reinterpret_cast<const float2*>(bias + 512 + j);
    float2 zg = *reinterpret_cast<const float2*>(bias + 1024 + j);
    float2 zo = *reinterpret_cast<const float2*>(bias + 1536 + j);
    const float* p = Zp + (long long)bt * G4H + j;
#pragma unroll
    for (int s = 0; s < NSL; s++) {
        const float* q = p + (long long)s * Bsz * G4H;
        float2 a = *reinterpret_cast<const float2*>(q);
        float2 b = *reinterpret_cast<const float2*>(q + 512);
        float2 c = *reinterpret_cast<const float2*>(q + 1024);
        float2 d = *reinterpret_cast<const float2*>(q + 1536);
        zi.x += a.x; zi.y += a.y;
        zf.x += b.x; zf.y += b.y;
        zg.x += c.x; zg.y += c.y;
        zo.x += d.x; zo.y += d.y;
    }
    int idx = bt * Hdim + j;
    float2 cp = *reinterpret_cast<const float2*>(c_prev + idx);
    float2 cv, hv;
    cv.x = sigmoidf_fast(zf.x) * cp.x + sigmoidf_fast(zi.x) * fmaxf(zg.x, 0.0f);
    cv.y = sigmoidf_fast(zf.y) * cp.y + sigmoidf_fast(zi.y) * fmaxf(zg.y, 0.0f);
    hv.x = sigmoidf_fast(zo.x) * fmaxf(cv.x, 0.0f);
    hv.y = sigmoidf_fast(zo.y) * fmaxf(cv.y, 0.0f);
    *reinterpret_cast<float2*>(c_new + idx) = cv;
    *reinterpret_cast<float2*>(h_new + idx) = hv;
    if (h_mir) {
        *reinterpret_cast<float2*>(h_mir + idx) = hv;
        *reinterpret_cast<float2*>(c_mir + idx) = cv;
    }
}

// ---------------------------------------------------------------------------
// Softmax over V=32000 per batch row (single logits slice + bias)
// ---------------------------------------------------------------------------
__global__ void softmax_kernel(const float* __restrict__ L,
                               const float* __restrict__ bd,
                               float* __restrict__ out)
{
    const int V = Vdim;
    int b = blockIdx.x;
    int tid = threadIdx.x;
    const float* r0 = L + (long long)b * V;

    float m = -1e30f, s = 0.0f;
    for (int v = tid; v < V; v += 512) {
        float val = r0[v] + bd[v];
        float nm = fmaxf(m, val);
        s = s * __expf(m - nm) + __expf(val - nm);
        m = nm;
    }
    __shared__ float sm[512], ss[512];
    sm[tid] = m; ss[tid] = s;
    __syncthreads();
    for (int st = 256; st > 0; st >>= 1) {
        if (tid < st) {
            float m2 = sm[tid + st], s2 = ss[tid + st];
            float nm = fmaxf(sm[tid], m2);
            ss[tid] = ss[tid] * __expf(sm[tid] - nm) + s2 * __expf(m2 - nm);
            sm[tid] = nm;
        }
        __syncthreads();
    }
    float M = sm[0];
    float Sinv = 1.0f / ss[0];
    for (int v = tid; v < V; v += 512) {
        float val = r0[v] + bd[v];
        out[(long long)b * V + v] = __expf(val - M) * Sinv;
    }
}

// ---------------------------------------------------------------------------
// kernel_launch
// ---------------------------------------------------------------------------
extern "C" void kernel_launch(void* const* d_in, const int* in_sizes, int n_in,
                              void* d_out, int out_size)
{
    const float* enc     = (const float*)d_in[0];
    const float* word    = (const float*)d_in[1];
    const float* h0      = (const float*)d_in[2];
    const float* c0      = (const float*)d_in[3];
    const float* persona = (const float*)d_in[4];
    const float* W1      = (const float*)d_in[5];
    const float* U1      = (const float*)d_in[6];
    const float* b1      = (const float*)d_in[7];
    const float* W2      = (const float*)d_in[8];
    const float* U2      = (const float*)d_in[9];
    const float* b2      = (const float*)d_in[10];
    const float* W3      = (const float*)d_in[11];
    const float* U3      = (const float*)d_in[12];
    const float* b3      = (const float*)d_in[13];
    const float* W4      = (const float*)d_in[14];
    const float* U4      = (const float*)d_in[15];
    const float* b4      = (const float*)d_in[16];
    const float* Wd      = (const float*)d_in[17];
    const float* bd      = (const float*)d_in[18];
    const int*   speaker = (const int*)d_in[19];
    float* out = (float*)d_out;

    void *pz, *ph, *pc, *pl;
    cudaGetSymbolAddress(&pz, g_zpart);
    cudaGetSymbolAddress(&ph, g_hbuf);
    cudaGetSymbolAddress(&pc, g_cbuf);
    cudaGetSymbolAddress(&pl, g_logits);
    float* zp = (float*)pz;
    float* hb = (float*)ph;
    float* cb = (float*)pc;
    float* lg = (float*)pl;
    float* h1b = hb;
    float* h2b = hb + Bsz * Hdim;
    float* c1b = cb;
    float* c2b = cb + Bsz * Hdim;

    const int GATE_GRID = (Bsz * Hdim / 2) / 128;   // 128 blocks

    // 5 spacers: puts the layer-1 GEMM at launch index 5 for ncu (-s 5 -c 1)
    for (int i = 0; i < 5; i++) noop_kernel<<<1, 32>>>();

    // layer 1: z = [x|h0] @ [W1;U1], K=11776, 8 splits of 1472, grid 32x8
    mma_gemm_kernel<1><<<dim3(32, 8), 128>>>(
        h0, 512, W1, U1, 11264, 1472, G4H, zp, enc, word, persona, speaker);
    gates_kernel<8><<<GATE_GRID, 128>>>(zp, b1, c0, h1b, c1b, nullptr, nullptr);

    // layers 2..4: z = [h|h] @ [W;U], K=1024, 2 splits of 512, grid 32x2
    mma_gemm_kernel<2><<<dim3(32, 2), 128>>>(
        h1b, 512, W2, U2, 512, 512, G4H, zp, nullptr, nullptr, nullptr, nullptr);
    gates_kernel<2><<<GATE_GRID, 128>>>(zp, b2, c1b, h2b, c2b, nullptr, nullptr);

    mma_gemm_kernel<2><<<dim3(32, 2), 128>>>(
        h2b, 512, W3, U3, 512, 512, G4H, zp, nullptr, nullptr, nullptr, nullptr);
    gates_kernel<2><<<GATE_GRID, 128>>>(zp, b3, c2b, h1b, c1b, nullptr, nullptr);

    mma_gemm_kernel<2><<<dim3(32, 2), 128>>>(
        h1b, 512, W4, U4, 512, 512, G4H, zp, nullptr, nullptr, nullptr, nullptr);
    gates_kernel<2><<<GATE_GRID, 128>>>(
        zp, b4, c1b, h2b, c2b,
        out + (long long)Bsz * Vdim,
        out + (long long)Bsz * Vdim + Bsz * Hdim);

    // decoder: logits = h4 @ Wd, grid 500, no split-K
    mma_gemm_kernel<0><<<dim3(500, 1), 128>>>(
        h2b, 512, Wd, Wd, 1 << 30, 512, Vdim, lg,
        nullptr, nullptr, nullptr, nullptr);

    // softmax -> probs
    softmax_kernel<<<Bsz, 512>>>(lg, bd, out);
}

// round 10
// speedup vs baseline: 1.7416x; 1.0246x over previous
#include <cuda_runtime.h>
#include <cuda_bf16.h>
#include <cstdint>

// ---------------------------------------------------------------------------
// Problem constants: B=64, S=20, E=512, H=512, V=32000, C=1000
//   D1 = 11264, virtual K1 = 11776 = [enc|word|persona|h0], 4H = 2048
// ---------------------------------------------------------------------------
#define Bsz   64
#define Hdim  512
#define G4H   2048
#define Vdim  32000
#define K1v   11776

static __device__ float g_zpart[8 * Bsz * G4H];            // 4.2 MB
static __device__ float g_hbuf[2][Bsz * Hdim];
static __device__ float g_cbuf[2][Bsz * Hdim];
static __device__ float g_logits[Bsz * Vdim];              // 8.2 MB
static __device__ __nv_bfloat16 g_x1h[Bsz * K1v];          // 1.5 MB: layer-1 A hi
static __device__ __nv_bfloat16 g_x1l[Bsz * K1v];          // 1.5 MB: layer-1 A lo
static __device__ __nv_bfloat16 g_hh[2][Bsz * Hdim];       // h bf16 hi (ping-pong)
static __device__ __nv_bfloat16 g_hl[2][Bsz * Hdim];       // h bf16 lo

__device__ __forceinline__ float sigmoidf_fast(float x) {
    return 1.0f / (1.0f + __expf(-x));
}
__device__ __forceinline__ uint32_t smem_u32(const void* p) {
    uint32_t a;
    asm("{ .reg .u64 t; cvta.to.shared.u64 t, %1; cvt.u32.u64 %0, t; }"
        : "=r"(a) : "l"(p));
    return a;
}
__device__ __forceinline__ void ldsm4(uint32_t* r, uint32_t addr) {
    asm volatile("ldmatrix.sync.aligned.m8n8.x4.shared.b16 {%0,%1,%2,%3}, [%4];"
                 : "=r"(r[0]), "=r"(r[1]), "=r"(r[2]), "=r"(r[3]) : "r"(addr));
}
__device__ __forceinline__ void ldsm4t(uint32_t* r, uint32_t addr) {
    asm volatile("ldmatrix.sync.aligned.m8n8.x4.trans.shared.b16 {%0,%1,%2,%3}, [%4];"
                 : "=r"(r[0]), "=r"(r[1]), "=r"(r[2]), "=r"(r[3]) : "r"(addr));
}
__device__ __forceinline__ void mma16816(float* d, const uint32_t* a,
                                         uint32_t b0, uint32_t b1) {
    asm volatile(
        "mma.sync.aligned.m16n8k16.row.col.f32.bf16.bf16.f32 "
        "{%0,%1,%2,%3}, {%4,%5,%6,%7}, {%8,%9}, {%0,%1,%2,%3};"
        : "+f"(d[0]), "+f"(d[1]), "+f"(d[2]), "+f"(d[3])
        : "r"(a[0]), "r"(a[1]), "r"(a[2]), "r"(a[3]), "r"(b0), "r"(b1));
}
// Dekker split of 2 floats -> packed bf16x2 hi + lo (rn-exact vs element-wise)
__device__ __forceinline__ void dek2(float x, float y, uint32_t& hp, uint32_t& lp) {
    asm("cvt.rn.bf16x2.f32 %0, %1, %2;" : "=r"(hp) : "f"(y), "f"(x));
    float fx = __uint_as_float(hp << 16);
    float fy = __uint_as_float(hp & 0xFFFF0000u);
    asm("cvt.rn.bf16x2.f32 %0, %1, %2;" : "=r"(lp) : "f"(y - fy), "f"(x - fx));
}

// ---------------------------------------------------------------------------
// xconv: build layer-1 A = [enc|word|persona[spk]|h0] as bf16 hi/lo planes.
// 8 floats per thread; 64 * 11776 / 8 = 94208 threads.
// ---------------------------------------------------------------------------
__global__ void xconv_kernel(const float* __restrict__ enc,
                             const float* __restrict__ word,
                             const float* __restrict__ persona,
                             const float* __restrict__ h0,
                             const int* __restrict__ speaker,
                             __nv_bfloat16* __restrict__ xh,
                             __nv_bfloat16* __restrict__ xl)
{
    int idx = blockIdx.x * 128 + threadIdx.x;      // < 94208
    int row = idx / (K1v / 8);
    int q = (idx - row * (K1v / 8)) * 8;
    const float* p;
    if (q < 10240)       p = enc + (long long)row * 10240 + q;
    else if (q < 10752)  p = word + (long long)row * 512 + (q - 10240);
    else if (q < 11264)  p = persona + (long long)speaker[row] * 512 + (q - 10752);
    else                 p = h0 + (long long)row * 512 + (q - 11264);
    float4 a = *reinterpret_cast<const float4*>(p);
    float4 b = *reinterpret_cast<const float4*>(p + 4);
    uint32_t h0p, l0p, h1p, l1p, h2p, l2p, h3p, l3p;
    dek2(a.x, a.y, h0p, l0p);
    dek2(a.z, a.w, h1p, l1p);
    dek2(b.x, b.y, h2p, l2p);
    dek2(b.z, b.w, h3p, l3p);
    long long o = (long long)row * K1v + q;
    *reinterpret_cast<uint4*>(xh + o) = make_uint4(h0p, h1p, h2p, h3p);
    *reinterpret_cast<uint4*>(xl + o) = make_uint4(l0p, l1p, l2p, l3p);
}

// ---------------------------------------------------------------------------
// bf16 Dekker-split warp-MMA GEMM.  M=64, TILE_N=64, BK=32, 128 threads.
//   Z[sp][m][n0+n] = sum_{k in [sp*kc,(sp+1)*kc)} X[m][k] * Wv[k][n]
// A: preconverted bf16 hi/lo planes (XSTRIDE row stride; WRAP: kg &= 511).
// W: fp32, converted in-loader. 3 Dekker streams into one fp32 acc set.
// Per warp: 64(M) x 16(N) strip = 4 Mtiles x 2 Ntiles of m16n8k16.
// ---------------------------------------------------------------------------
template<int XSTRIDE, bool WRAP>
__global__ __launch_bounds__(128, 3) void mma_gemm_kernel(
    const __nv_bfloat16* __restrict__ Xh, const __nv_bfloat16* __restrict__ Xl,
    const float* __restrict__ Wa, const float* __restrict__ Wb, int wsplit,
    int kc, int N, float* __restrict__ Zall)
{
    __shared__ __align__(16) __nv_bfloat16 Ah[2][64][40];  // stride 80B
    __shared__ __align__(16) __nv_bfloat16 Al[2][64][40];
    __shared__ __align__(16) __nv_bfloat16 Bh[2][32][72];  // stride 144B
    __shared__ __align__(16) __nv_bfloat16 Bl[2][32][72];

    const int tid = threadIdx.x;
    const int lane = tid & 31;
    const int warp = tid >> 5;
    const int n0 = blockIdx.x * 64;
    const int sp = blockIdx.y;
    const int k0 = sp * kc;
    float* Z = Zall + (long long)sp * 64 * N;

    // A loader: row xm (0..63), k window xh2 in {0,16} (16 elements per thread)
    const int xm = tid >> 1;
    const int xh2 = (tid & 1) * 16;
    const __nv_bfloat16* xhp = Xh + (long long)xm * XSTRIDE;
    const __nv_bfloat16* xlp = Xl + (long long)xm * XSTRIDE;
    // B loader: k-row bk (0..31), n segment bn in {0,16,32,48}
    const int bk = tid >> 2;
    const int bn = (tid & 3) * 16;

    uint4 avh0, avh1, avl0, avl1;      // 16 bf16 per plane = 2 x uint4
    float4 br[4];
    auto loadA = [&](int t) {
        int kg = k0 + t * 32 + xh2;
        if (WRAP) kg &= 511;
        avh0 = *reinterpret_cast<const uint4*>(xhp + kg);
        avh1 = *reinterpret_cast<const uint4*>(xhp + kg + 8);
        avl0 = *reinterpret_cast<const uint4*>(xlp + kg);
        avl1 = *reinterpret_cast<const uint4*>(xlp + kg + 8);
    };
    auto loadB = [&](int t) {
        int r = k0 + t * 32 + bk;
        const float* p = (r < wsplit) ? (Wa + (long long)r * N)
                                      : (Wb + (long long)(r - wsplit) * N);
#pragma unroll
        for (int i = 0; i < 4; i++)
            br[i] = *reinterpret_cast<const float4*>(p + n0 + bn + i * 4);
    };
    auto storeA = [&](int b) {
        *reinterpret_cast<uint4*>(&Ah[b][xm][xh2])     = avh0;
        *reinterpret_cast<uint4*>(&Ah[b][xm][xh2 + 8]) = avh1;
        *reinterpret_cast<uint4*>(&Al[b][xm][xh2])     = avl0;
        *reinterpret_cast<uint4*>(&Al[b][xm][xh2 + 8]) = avl1;
    };
    auto storeB = [&](int b) {
#pragma unroll
        for (int i = 0; i < 4; i++) {
            float4 v = br[i];
            uint32_t h01, l01, h23, l23;
            dek2(v.x, v.y, h01, l01);
            dek2(v.z, v.w, h23, l23);
            *reinterpret_cast<uint2*>(&Bh[b][bk][bn + i * 4]) = make_uint2(h01, h23);
            *reinterpret_cast<uint2*>(&Bl[b][bk][bn + i * 4]) = make_uint2(l01, l23);
        }
    };

    float acc[4][2][4];
#pragma unroll
    for (int mt = 0; mt < 4; mt++)
#pragma unroll
        for (int nt = 0; nt < 2; nt++)
#pragma unroll
            for (int e = 0; e < 4; e++) acc[mt][nt][e] = 0.0f;

    const int NT = kc >> 5;     // BK = 32
    loadA(0); loadB(0);
    storeA(0); storeB(0);
    __syncthreads();

    const int nw = warp * 16;
    const int lr = lane & 15;
    const int lc = (lane >> 4) * 8;

    for (int t = 0; t < NT; t++) {
        const int buf = t & 1;
        const bool has_next = (t + 1 < NT);
        if (has_next) { loadA(t + 1); loadB(t + 1); }

#pragma unroll
        for (int s = 0; s < 2; s++) {
            uint32_t bhf[4], blf[4];
            ldsm4t(bhf, smem_u32(&Bh[buf][s * 16 + lr][nw + lc]));
            ldsm4t(blf, smem_u32(&Bl[buf][s * 16 + lr][nw + lc]));
#pragma unroll
            for (int mt = 0; mt < 4; mt++) {
                uint32_t ahf[4], alf[4];
                ldsm4(ahf, smem_u32(&Ah[buf][mt * 16 + lr][s * 16 + lc]));
                ldsm4(alf, smem_u32(&Al[buf][mt * 16 + lr][s * 16 + lc]));
                mma16816(acc[mt][0], ahf, bhf[0], bhf[1]);
                mma16816(acc[mt][1], ahf, bhf[2], bhf[3]);
                mma16816(acc[mt][0], ahf, blf[0], blf[1]);
                mma16816(acc[mt][1], ahf, blf[2], blf[3]);
                mma16816(acc[mt][0], alf, bhf[0], bhf[1]);
                mma16816(acc[mt][1], alf, bhf[2], bhf[3]);
            }
        }
        if (has_next) { storeA((t + 1) & 1); storeB((t + 1) & 1); }
        __syncthreads();
    }

    // epilogue
#pragma unroll
    for (int mt = 0; mt < 4; mt++)
#pragma unroll
        for (int nt = 0; nt < 2; nt++) {
            int row = mt * 16 + (lane >> 2);
            int col = n0 + nw + nt * 8 + (lane & 3) * 2;
            *reinterpret_cast<float2*>(&Z[(long long)row * N + col]) =
                make_float2(acc[mt][nt][0], acc[mt][nt][1]);
            *reinterpret_cast<float2*>(&Z[(long long)(row + 8) * N + col]) =
                make_float2(acc[mt][nt][2], acc[mt][nt][3]);
        }
}

// ---------------------------------------------------------------------------
// Gate kernel (float2): reduce NSL split slices + bias, Keras LSTM cell.
// Emits h as fp32 AND packed bf16 hi/lo (for the next GEMM's A operand).
// ---------------------------------------------------------------------------
template<int NSL>
__global__ void gates_kernel(const float* __restrict__ Zp,
                             const float* __restrict__ bias,
                             const float* __restrict__ c_prev,
                             float* __restrict__ h_new,
                             float* __restrict__ c_new,
                             uint32_t* __restrict__ hh_out,
                             uint32_t* __restrict__ hl_out,
                             float* __restrict__ h_mir,
                             float* __restrict__ c_mir)
{
    int p2 = blockIdx.x * 128 + threadIdx.x;
    if (p2 >= Bsz * (Hdim / 2)) return;
    int bt = p2 >> 8;
    int j = (p2 & 255) * 2;

    float2 zi = *reinterpret_cast<const float2*>(bias + j);
    float2 zf = *reinterpret_cast<const float2*>(bias + 512 + j);
    float2 zg = *reinterpret_cast<const float2*>(bias + 1024 + j);
    float2 zo = *reinterpret_cast<const float2*>(bias + 1536 + j);
    const float* p = Zp + (long long)bt * G4H + j;
#pragma unroll
    for (int s = 0; s < NSL; s++) {
        const float* q = p + (long long)s * Bsz * G4H;
        float2 a = *reinterpret_cast<const float2*>(q);
        float2 b = *reinterpret_cast<const float2*>(q + 512);
        float2 c = *reinterpret_cast<const float2*>(q + 1024);
        float2 d = *reinterpret_cast<const float2*>(q + 1536);
        zi.x += a.x; zi.y += a.y;
        zf.x += b.x; zf.y += b.y;
        zg.x += c.x; zg.y += c.y;
        zo.x += d.x; zo.y += d.y;
    }
    int idx = bt * Hdim + j;
    float2 cp = *reinterpret_cast<const float2*>(c_prev + idx);
    float2 cv, hv;
    cv.x = sigmoidf_fast(zf.x) * cp.x + sigmoidf_fast(zi.x) * fmaxf(zg.x, 0.0f);
    cv.y = sigmoidf_fast(zf.y) * cp.y + sigmoidf_fast(zi.y) * fmaxf(zg.y, 0.0f);
    hv.x = sigmoidf_fast(zo.x) * fmaxf(cv.x, 0.0f);
    hv.y = sigmoidf_fast(zo.y) * fmaxf(cv.y, 0.0f);
    *reinterpret_cast<float2*>(c_new + idx) = cv;
    *reinterpret_cast<float2*>(h_new + idx) = hv;
    uint32_t hp, lp;
    dek2(hv.x, hv.y, hp, lp);
    hh_out[p2] = hp;
    hl_out[p2] = lp;
    if (h_mir) {
        *reinterpret_cast<float2*>(h_mir + idx) = hv;
        *reinterpret_cast<float2*>(c_mir + idx) = cv;
    }
}

// ---------------------------------------------------------------------------
// Softmax over V=32000 per batch row
// ---------------------------------------------------------------------------
__global__ void softmax_kernel(const float* __restrict__ L,
                               const float* __restrict__ bd,
                               float* __restrict__ out)
{
    const int V = Vdim;
    int b = blockIdx.x;
    int tid = threadIdx.x;
    const float* r0 = L + (long long)b * V;

    float m = -1e30f, s = 0.0f;
    for (int v = tid; v < V; v += 512) {
        float val = r0[v] + bd[v];
        float nm = fmaxf(m, val);
        s = s * __expf(m - nm) + __expf(val - nm);
        m = nm;
    }
    __shared__ float sm[512], ss[512];
    sm[tid] = m; ss[tid] = s;
    __syncthreads();
    for (int st = 256; st > 0; st >>= 1) {
        if (tid < st) {
            float m2 = sm[tid + st], s2 = ss[tid + st];
            float nm = fmaxf(sm[tid], m2);
            ss[tid] = ss[tid] * __expf(sm[tid] - nm) + s2 * __expf(m2 - nm);
            sm[tid] = nm;
        }
        __syncthreads();
    }
    float M = sm[0];
    float Sinv = 1.0f / ss[0];
    for (int v = tid; v < V; v += 512) {
        float val = r0[v] + bd[v];
        out[(long long)b * V + v] = __expf(val - M) * Sinv;
    }
}

// ---------------------------------------------------------------------------
// kernel_launch
// ---------------------------------------------------------------------------
extern "C" void kernel_launch(void* const* d_in, const int* in_sizes, int n_in,
                              void* d_out, int out_size)
{
    const float* enc     = (const float*)d_in[0];
    const float* word    = (const float*)d_in[1];
    const float* h0      = (const float*)d_in[2];
    const float* c0      = (const float*)d_in[3];
    const float* persona = (const float*)d_in[4];
    const float* W1      = (const float*)d_in[5];
    const float* U1      = (const float*)d_in[6];
    const float* b1      = (const float*)d_in[7];
    const float* W2      = (const float*)d_in[8];
    const float* U2      = (const float*)d_in[9];
    const float* b2      = (const float*)d_in[10];
    const float* W3      = (const float*)d_in[11];
    const float* U3      = (const float*)d_in[12];
    const float* b3      = (const float*)d_in[13];
    const float* W4      = (const float*)d_in[14];
    const float* U4      = (const float*)d_in[15];
    const float* b4      = (const float*)d_in[16];
    const float* Wd      = (const float*)d_in[17];
    const float* bd      = (const float*)d_in[18];
    const int*   speaker = (const int*)d_in[19];
    float* out = (float*)d_out;

    void *pz, *ph, *pc, *pl, *pxh, *pxl, *phh, *phl;
    cudaGetSymbolAddress(&pz, g_zpart);
    cudaGetSymbolAddress(&ph, g_hbuf);
    cudaGetSymbolAddress(&pc, g_cbuf);
    cudaGetSymbolAddress(&pl, g_logits);
    cudaGetSymbolAddress(&pxh, g_x1h);
    cudaGetSymbolAddress(&pxl, g_x1l);
    cudaGetSymbolAddress(&phh, g_hh);
    cudaGetSymbolAddress(&phl, g_hl);
    float* zp = (float*)pz;
    float* hb = (float*)ph;
    float* cb = (float*)pc;
    float* lg = (float*)pl;
    __nv_bfloat16* x1h = (__nv_bfloat16*)pxh;
    __nv_bfloat16* x1l = (__nv_bfloat16*)pxl;
    __nv_bfloat16* hh0 = (__nv_bfloat16*)phh;
    __nv_bfloat16* hh1 = hh0 + Bsz * Hdim;
    __nv_bfloat16* hl0 = (__nv_bfloat16*)phl;
    __nv_bfloat16* hl1 = hl0 + Bsz * Hdim;
    float* h1b = hb;
    float* h2b = hb + Bsz * Hdim;
    float* c1b = cb;
    float* c2b = cb + Bsz * Hdim;

    const int GATE_GRID = (Bsz * Hdim / 2) / 128;   // 128 blocks

    // 0) layer-1 A -> bf16 hi/lo planes
    xconv_kernel<<<(Bsz * K1v / 8 + 127) / 128, 128>>>(
        enc, word, persona, h0, speaker, x1h, x1l);

    // 1) layer 1: z = [x|h0] @ [W1;U1], K=11776, 8 splits of 1472, grid 32x8
    mma_gemm_kernel<K1v, false><<<dim3(32, 8), 128>>>(
        x1h, x1l, W1, U1, 11264, 1472, G4H, zp);
    gates_kernel<8><<<GATE_GRID, 128>>>(zp, b1, c0, h1b, c1b,
        (uint32_t*)hh0, (uint32_t*)hl0, nullptr, nullptr);

    // 2) layers 2..4: z = [h|h] @ [W;U], K=1024, 2 splits of 512, grid 32x2
    mma_gemm_kernel<Hdim, true><<<dim3(32, 2), 128>>>(
        hh0, hl0, W2, U2, 512, 512, G4H, zp);
    gates_kernel<2><<<GATE_GRID, 128>>>(zp, b2, c1b, h2b, c2b,
        (uint32_t*)hh1, (uint32_t*)hl1, nullptr, nullptr);

    mma_gemm_kernel<Hdim, true><<<dim3(32, 2), 128>>>(
        hh1, hl1, W3, U3, 512, 512, G4H, zp);
    gates_kernel<2><<<GATE_GRID, 128>>>(zp, b3, c2b, h1b, c1b,
        (uint32_t*)hh0, (uint32_t*)hl0, nullptr, nullptr);

    mma_gemm_kernel<Hdim, true><<<dim3(32, 2), 128>>>(
        hh0, hl0, W4, U4, 512, 512, G4H, zp);
    gates_kernel<2><<<GATE_GRID, 128>>>(zp, b4, c1b, h2b, c2b,
        (uint32_t*)hh1, (uint32_t*)hl1,
        out + (long long)Bsz * Vdim,
        out + (long long)Bsz * Vdim + Bsz * Hdim);

    // 3) decoder: logits = h4 @ Wd, grid 500, no split-K
    mma_gemm_kernel<Hdim, true><<<dim3(500, 1), 128>>>(
        hh1, hl1, Wd, Wd, 1 << 30, 512, Vdim, lg);

    // 4) softmax -> probs
    softmax_kernel<<<Bsz, 512>>>(lg, bd, out);
}

// round 11
// speedup vs baseline: 1.9134x; 1.0986x over previous
#include <cuda_runtime.h>
#include <cuda_bf16.h>
#include <cstdint>

// ---------------------------------------------------------------------------
// Problem constants: B=64, S=20, E=512, H=512, V=32000, C=1000
//   D1 = 11264, virtual K1 = 11776 = [enc|word|persona|h0], 4H = 2048
// ---------------------------------------------------------------------------
#define Bsz   64
#define Hdim  512
#define G4H   2048
#define Vdim  32000
#define K1v   11776

static __device__ float g_zpart[16 * Bsz * G4H];           // 8.4 MB (16 slices)
static __device__ float g_hbuf[2][Bsz * Hdim];
static __device__ float g_cbuf[2][Bsz * Hdim];
static __device__ float g_logits[Bsz * Vdim];              // 8.2 MB
static __device__ __nv_bfloat16 g_x1h[Bsz * K1v];          // 1.5 MB: layer-1 A hi
static __device__ __nv_bfloat16 g_x1l[Bsz * K1v];          // 1.5 MB: layer-1 A lo
static __device__ __nv_bfloat16 g_hh[2][Bsz * Hdim];       // h bf16 hi (ping-pong)
static __device__ __nv_bfloat16 g_hl[2][Bsz * Hdim];       // h bf16 lo

__device__ __forceinline__ float sigmoidf_fast(float x) {
    return 1.0f / (1.0f + __expf(-x));
}
__device__ __forceinline__ uint32_t smem_u32(const void* p) {
    uint32_t a;
    asm("{ .reg .u64 t; cvta.to.shared.u64 t, %1; cvt.u32.u64 %0, t; }"
        : "=r"(a) : "l"(p));
    return a;
}
__device__ __forceinline__ void ldsm4(uint32_t* r, uint32_t addr) {
    asm volatile("ldmatrix.sync.aligned.m8n8.x4.shared.b16 {%0,%1,%2,%3}, [%4];"
                 : "=r"(r[0]), "=r"(r[1]), "=r"(r[2]), "=r"(r[3]) : "r"(addr));
}
__device__ __forceinline__ void ldsm4t(uint32_t* r, uint32_t addr) {
    asm volatile("ldmatrix.sync.aligned.m8n8.x4.trans.shared.b16 {%0,%1,%2,%3}, [%4];"
                 : "=r"(r[0]), "=r"(r[1]), "=r"(r[2]), "=r"(r[3]) : "r"(addr));
}
__device__ __forceinline__ void mma16816(float* d, const uint32_t* a,
                                         uint32_t b0, uint32_t b1) {
    asm volatile(
        "mma.sync.aligned.m16n8k16.row.col.f32.bf16.bf16.f32 "
        "{%0,%1,%2,%3}, {%4,%5,%6,%7}, {%8,%9}, {%0,%1,%2,%3};"
        : "+f"(d[0]), "+f"(d[1]), "+f"(d[2]), "+f"(d[3])
        : "r"(a[0]), "r"(a[1]), "r"(a[2]), "r"(a[3]), "r"(b0), "r"(b1));
}
// Dekker split of 2 floats -> packed bf16x2 hi + lo (rn-exact vs element-wise)
__device__ __forceinline__ void dek2(float x, float y, uint32_t& hp, uint32_t& lp) {
    asm("cvt.rn.bf16x2.f32 %0, %1, %2;" : "=r"(hp) : "f"(y), "f"(x));
    float fx = __uint_as_float(hp << 16);
    float fy = __uint_as_float(hp & 0xFFFF0000u);
    asm("cvt.rn.bf16x2.f32 %0, %1, %2;" : "=r"(lp) : "f"(y - fy), "f"(x - fx));
}

// ---------------------------------------------------------------------------
// xconv: build layer-1 A = [enc|word|persona[spk]|h0] as bf16 hi/lo planes.
// ---------------------------------------------------------------------------
__global__ void xconv_kernel(const float* __restrict__ enc,
                             const float* __restrict__ word,
                             const float* __restrict__ persona,
                             const float* __restrict__ h0,
                             const int* __restrict__ speaker,
                             __nv_bfloat16* __restrict__ xh,
                             __nv_bfloat16* __restrict__ xl)
{
    int idx = blockIdx.x * 128 + threadIdx.x;      // < 94208
    int row = idx / (K1v / 8);
    int q = (idx - row * (K1v / 8)) * 8;
    const float* p;
    if (q < 10240)       p = enc + (long long)row * 10240 + q;
    else if (q < 10752)  p = word + (long long)row * 512 + (q - 10240);
    else if (q < 11264)  p = persona + (long long)speaker[row] * 512 + (q - 10752);
    else                 p = h0 + (long long)row * 512 + (q - 11264);
    float4 a = *reinterpret_cast<const float4*>(p);
    float4 b = *reinterpret_cast<const float4*>(p + 4);
    uint32_t h0p, l0p, h1p, l1p, h2p, l2p, h3p, l3p;
    dek2(a.x, a.y, h0p, l0p);
    dek2(a.z, a.w, h1p, l1p);
    dek2(b.x, b.y, h2p, l2p);
    dek2(b.z, b.w, h3p, l3p);
    long long o = (long long)row * K1v + q;
    *reinterpret_cast<uint4*>(xh + o) = make_uint4(h0p, h1p, h2p, h3p);
    *reinterpret_cast<uint4*>(xl + o) = make_uint4(l0p, l1p, l2p, l3p);
}

// ---------------------------------------------------------------------------
// bf16 Dekker-split warp-MMA GEMM.  M=64, TILE_N=64, BK=32, 128 threads.
//   Z[sp][m][n0+n] = sum_{k in [sp*kc,(sp+1)*kc)} X[m][k] * Wv[k][n]
// A: preconverted bf16 hi/lo planes (XSTRIDE row stride; WRAP: kg &= 511).
// W: fp32, converted in-loader. 3 Dekker streams into one fp32 acc set.
// Per warp: 64(M) x 16(N) strip = 4 Mtiles x 2 Ntiles of m16n8k16.
// ---------------------------------------------------------------------------
template<int XSTRIDE, bool WRAP>
__global__ __launch_bounds__(128, 3) void mma_gemm_kernel(
    const __nv_bfloat16* __restrict__ Xh, const __nv_bfloat16* __restrict__ Xl,
    const float* __restrict__ Wa, const float* __restrict__ Wb, int wsplit,
    int kc, int N, float* __restrict__ Zall)
{
    __shared__ __align__(16) __nv_bfloat16 Ah[2][64][40];  // stride 80B
    __shared__ __align__(16) __nv_bfloat16 Al[2][64][40];
    __shared__ __align__(16) __nv_bfloat16 Bh[2][32][72];  // stride 144B
    __shared__ __align__(16) __nv_bfloat16 Bl[2][32][72];

    const int tid = threadIdx.x;
    const int lane = tid & 31;
    const int warp = tid >> 5;
    const int n0 = blockIdx.x * 64;
    const int sp = blockIdx.y;
    const int k0 = sp * kc;
    float* Z = Zall + (long long)sp * 64 * N;

    // A loader: row xm (0..63), k window xh2 in {0,16} (16 elements per thread)
    const int xm = tid >> 1;
    const int xh2 = (tid & 1) * 16;
    const __nv_bfloat16* xhp = Xh + (long long)xm * XSTRIDE;
    const __nv_bfloat16* xlp = Xl + (long long)xm * XSTRIDE;
    // B loader: k-row bk (0..31), n segment bn in {0,16,32,48}
    const int bk = tid >> 2;
    const int bn = (tid & 3) * 16;

    uint4 avh0, avh1, avl0, avl1;      // 16 bf16 per plane = 2 x uint4
    float4 br[4];
    auto loadA = [&](int t) {
        int kg = k0 + t * 32 + xh2;
        if (WRAP) kg &= 511;
        avh0 = *reinterpret_cast<const uint4*>(xhp + kg);
        avh1 = *reinterpret_cast<const uint4*>(xhp + kg + 8);
        avl0 = *reinterpret_cast<const uint4*>(xlp + kg);
        avl1 = *reinterpret_cast<const uint4*>(xlp + kg + 8);
    };
    auto loadB = [&](int t) {
        int r = k0 + t * 32 + bk;
        const float* p = (r < wsplit) ? (Wa + (long long)r * N)
                                      : (Wb + (long long)(r - wsplit) * N);
#pragma unroll
        for (int i = 0; i < 4; i++)
            br[i] = *reinterpret_cast<const float4*>(p + n0 + bn + i * 4);
    };
    auto storeA = [&](int b) {
        *reinterpret_cast<uint4*>(&Ah[b][xm][xh2])     = avh0;
        *reinterpret_cast<uint4*>(&Ah[b][xm][xh2 + 8]) = avh1;
        *reinterpret_cast<uint4*>(&Al[b][xm][xh2])     = avl0;
        *reinterpret_cast<uint4*>(&Al[b][xm][xh2 + 8]) = avl1;
    };
    auto storeB = [&](int b) {
#pragma unroll
        for (int i = 0; i < 4; i++) {
            float4 v = br[i];
            uint32_t h01, l01, h23, l23;
            dek2(v.x, v.y, h01, l01);
            dek2(v.z, v.w, h23, l23);
            *reinterpret_cast<uint2*>(&Bh[b][bk][bn + i * 4]) = make_uint2(h01, h23);
            *reinterpret_cast<uint2*>(&Bl[b][bk][bn + i * 4]) = make_uint2(l01, l23);
        }
    };

    float acc[4][2][4];
#pragma unroll
    for (int mt = 0; mt < 4; mt++)
#pragma unroll
        for (int nt = 0; nt < 2; nt++)
#pragma unroll
            for (int e = 0; e < 4; e++) acc[mt][nt][e] = 0.0f;

    const int NT = kc >> 5;     // BK = 32
    loadA(0); loadB(0);
    storeA(0); storeB(0);
    __syncthreads();

    const int nw = warp * 16;
    const int lr = lane & 15;
    const int lc = (lane >> 4) * 8;

    for (int t = 0; t < NT; t++) {
        const int buf = t & 1;
        const bool has_next = (t + 1 < NT);
        if (has_next) { loadA(t + 1); loadB(t + 1); }

#pragma unroll
        for (int s = 0; s < 2; s++) {
            uint32_t bhf[4], blf[4];
            ldsm4t(bhf, smem_u32(&Bh[buf][s * 16 + lr][nw + lc]));
            ldsm4t(blf, smem_u32(&Bl[buf][s * 16 + lr][nw + lc]));
#pragma unroll
            for (int mt = 0; mt < 4; mt++) {
                uint32_t ahf[4], alf[4];
                ldsm4(ahf, smem_u32(&Ah[buf][mt * 16 + lr][s * 16 + lc]));
                ldsm4(alf, smem_u32(&Al[buf][mt * 16 + lr][s * 16 + lc]));
                mma16816(acc[mt][0], ahf, bhf[0], bhf[1]);
                mma16816(acc[mt][1], ahf, bhf[2], bhf[3]);
                mma16816(acc[mt][0], ahf, blf[0], blf[1]);
                mma16816(acc[mt][1], ahf, blf[2], blf[3]);
                mma16816(acc[mt][0], alf, bhf[0], bhf[1]);
                mma16816(acc[mt][1], alf, bhf[2], bhf[3]);
            }
        }
        if (has_next) { storeA((t + 1) & 1); storeB((t + 1) & 1); }
        __syncthreads();
    }

    // epilogue
#pragma unroll
    for (int mt = 0; mt < 4; mt++)
#pragma unroll
        for (int nt = 0; nt < 2; nt++) {
            int row = mt * 16 + (lane >> 2);
            int col = n0 + nw + nt * 8 + (lane & 3) * 2;
            *reinterpret_cast<float2*>(&Z[(long long)row * N + col]) =
                make_float2(acc[mt][nt][0], acc[mt][nt][1]);
            *reinterpret_cast<float2*>(&Z[(long long)(row + 8) * N + col]) =
                make_float2(acc[mt][nt][2], acc[mt][nt][3]);
        }
}

// ---------------------------------------------------------------------------
// Gate kernel (float2): reduce NSL split slices + bias, Keras LSTM cell.
// Emits h as fp32 AND packed bf16 hi/lo (for the next GEMM's A operand).
// ---------------------------------------------------------------------------
template<int NSL>
__global__ void gates_kernel(const float* __restrict__ Zp,
                             const float* __restrict__ bias,
                             const float* __restrict__ c_prev,
                             float* __restrict__ h_new,
                             float* __restrict__ c_new,
                             uint32_t* __restrict__ hh_out,
                             uint32_t* __restrict__ hl_out,
                             float* __restrict__ h_mir,
                             float* __restrict__ c_mir)
{
    int p2 = blockIdx.x * 128 + threadIdx.x;
    if (p2 >= Bsz * (Hdim / 2)) return;
    int bt = p2 >> 8;
    int j = (p2 & 255) * 2;

    float2 zi = *reinterpret_cast<const float2*>(bias + j);
    float2 zf = *reinterpret_cast<const float2*>(bias + 512 + j);
    float2 zg = *reinterpret_cast<const float2*>(bias + 1024 + j);
    float2 zo = *reinterpret_cast<const float2*>(bias + 1536 + j);
    const float* p = Zp + (long long)bt * G4H + j;
#pragma unroll
    for (int s = 0; s < NSL; s++) {
        const float* q = p + (long long)s * Bsz * G4H;
        float2 a = *reinterpret_cast<const float2*>(q);
        float2 b = *reinterpret_cast<const float2*>(q + 512);
        float2 c = *reinterpret_cast<const float2*>(q + 1024);
        float2 d = *reinterpret_cast<const float2*>(q + 1536);
        zi.x += a.x; zi.y += a.y;
        zf.x += b.x; zf.y += b.y;
        zg.x += c.x; zg.y += c.y;
        zo.x += d.x; zo.y += d.y;
    }
    int idx = bt * Hdim + j;
    float2 cp = *reinterpret_cast<const float2*>(c_prev + idx);
    float2 cv, hv;
    cv.x = sigmoidf_fast(zf.x) * cp.x + sigmoidf_fast(zi.x) * fmaxf(zg.x, 0.0f);
    cv.y = sigmoidf_fast(zf.y) * cp.y + sigmoidf_fast(zi.y) * fmaxf(zg.y, 0.0f);
    hv.x = sigmoidf_fast(zo.x) * fmaxf(cv.x, 0.0f);
    hv.y = sigmoidf_fast(zo.y) * fmaxf(cv.y, 0.0f);
    *reinterpret_cast<float2*>(c_new + idx) = cv;
    *reinterpret_cast<float2*>(h_new + idx) = hv;
    uint32_t hp, lp;
    dek2(hv.x, hv.y, hp, lp);
    hh_out[p2] = hp;
    hl_out[p2] = lp;
    if (h_mir) {
        *reinterpret_cast<float2*>(h_mir + idx) = hv;
        *reinterpret_cast<float2*>(c_mir + idx) = cv;
    }
}

// ---------------------------------------------------------------------------
// Softmax over V=32000 per batch row
// ---------------------------------------------------------------------------
__global__ void softmax_kernel(const float* __restrict__ L,
                               const float* __restrict__ bd,
                               float* __restrict__ out)
{
    const int V = Vdim;
    int b = blockIdx.x;
    int tid = threadIdx.x;
    const float* r0 = L + (long long)b * V;

    float m = -1e30f, s = 0.0f;
    for (int v = tid; v < V; v += 512) {
        float val = r0[v] + bd[v];
        float nm = fmaxf(m, val);
        s = s * __expf(m - nm) + __expf(val - nm);
        m = nm;
    }
    __shared__ float sm[512], ss[512];
    sm[tid] = m; ss[tid] = s;
    __syncthreads();
    for (int st = 256; st > 0; st >>= 1) {
        if (tid < st) {
            float m2 = sm[tid + st], s2 = ss[tid + st];
            float nm = fmaxf(sm[tid], m2);
            ss[tid] = ss[tid] * __expf(sm[tid] - nm) + s2 * __expf(m2 - nm);
            sm[tid] = nm;
        }
        __syncthreads();
    }
    float M = sm[0];
    float Sinv = 1.0f / ss[0];
    for (int v = tid; v < V; v += 512) {
        float val = r0[v] + bd[v];
        out[(long long)b * V + v] = __expf(val - M) * Sinv;
    }
}

// ---------------------------------------------------------------------------
// kernel_launch
// ---------------------------------------------------------------------------
extern "C" void kernel_launch(void* const* d_in, const int* in_sizes, int n_in,
                              void* d_out, int out_size)
{
    const float* enc     = (const float*)d_in[0];
    const float* word    = (const float*)d_in[1];
    const float* h0      = (const float*)d_in[2];
    const float* c0      = (const float*)d_in[3];
    const float* persona = (const float*)d_in[4];
    const float* W1      = (const float*)d_in[5];
    const float* U1      = (const float*)d_in[6];
    const float* b1      = (const float*)d_in[7];
    const float* W2      = (const float*)d_in[8];
    const float* U2      = (const float*)d_in[9];
    const float* b2      = (const float*)d_in[10];
    const float* W3      = (const float*)d_in[11];
    const float* U3      = (const float*)d_in[12];
    const float* b3      = (const float*)d_in[13];
    const float* W4      = (const float*)d_in[14];
    const float* U4      = (const float*)d_in[15];
    const float* b4      = (const float*)d_in[16];
    const float* Wd      = (const float*)d_in[17];
    const float* bd      = (const float*)d_in[18];
    const int*   speaker = (const int*)d_in[19];
    float* out = (float*)d_out;

    void *pz, *ph, *pc, *pl, *pxh, *pxl, *phh, *phl;
    cudaGetSymbolAddress(&pz, g_zpart);
    cudaGetSymbolAddress(&ph, g_hbuf);
    cudaGetSymbolAddress(&pc, g_cbuf);
    cudaGetSymbolAddress(&pl, g_logits);
    cudaGetSymbolAddress(&pxh, g_x1h);
    cudaGetSymbolAddress(&pxl, g_x1l);
    cudaGetSymbolAddress(&phh, g_hh);
    cudaGetSymbolAddress(&phl, g_hl);
    float* zp = (float*)pz;
    float* hb = (float*)ph;
    float* cb = (float*)pc;
    float* lg = (float*)pl;
    __nv_bfloat16* x1h = (__nv_bfloat16*)pxh;
    __nv_bfloat16* x1l = (__nv_bfloat16*)pxl;
    __nv_bfloat16* hh0 = (__nv_bfloat16*)phh;
    __nv_bfloat16* hh1 = hh0 + Bsz * Hdim;
    __nv_bfloat16* hl0 = (__nv_bfloat16*)phl;
    __nv_bfloat16* hl1 = hl0 + Bsz * Hdim;
    float* h1b = hb;
    float* h2b = hb + Bsz * Hdim;
    float* c1b = cb;
    float* c2b = cb + Bsz * Hdim;

    const int GATE_GRID = (Bsz * Hdim / 2) / 128;   // 128 blocks

    // 0) layer-1 A -> bf16 hi/lo planes
    xconv_kernel<<<(Bsz * K1v / 8 + 127) / 128, 128>>>(
        enc, word, persona, h0, speaker, x1h, x1l);

    // 1) layer 1: z = [x|h0] @ [W1;U1], K=11776, 16 splits of 736, grid 32x16
    mma_gemm_kernel<K1v, false><<<dim3(32, 16), 128>>>(
        x1h, x1l, W1, U1, 11264, 736, G4H, zp);
    gates_kernel<16><<<GATE_GRID, 128>>>(zp, b1, c0, h1b, c1b,
        (uint32_t*)hh0, (uint32_t*)hl0, nullptr, nullptr);

    // 2) layers 2..4: z = [h|h] @ [W;U], K=1024, 8 splits of 128, grid 32x8
    mma_gemm_kernel<Hdim, true><<<dim3(32, 8), 128>>>(
        hh0, hl0, W2, U2, 512, 128, G4H, zp);
    gates_kernel<8><<<GATE_GRID, 128>>>(zp, b2, c1b, h2b, c2b,
        (uint32_t*)hh1, (uint32_t*)hl1, nullptr, nullptr);

    mma_gemm_kernel<Hdim, true><<<dim3(32, 8), 128>>>(
        hh1, hl1, W3, U3, 512, 128, G4H, zp);
    gates_kernel<8><<<GATE_GRID, 128>>>(zp, b3, c2b, h1b, c1b,
        (uint32_t*)hh0, (uint32_t*)hl0, nullptr, nullptr);

    mma_gemm_kernel<Hdim, true><<<dim3(32, 8), 128>>>(
        hh0, hl0, W4, U4, 512, 128, G4H, zp);
    gates_kernel<8><<<GATE_GRID, 128>>>(zp, b4, c1b, h2b, c2b,
        (uint32_t*)hh1, (uint32_t*)hl1,
        out + (long long)Bsz * Vdim,
        out + (long long)Bsz * Vdim + Bsz * Hdim);

    // 3) decoder: logits = h4 @ Wd, grid 500, no split-K
    mma_gemm_kernel<Hdim, true><<<dim3(500, 1), 128>>>(
        hh1, hl1, Wd, Wd, 1 << 30, 512, Vdim, lg);

    // 4) softmax -> probs
    softmax_kernel<<<Bsz, 512>>>(lg, bd, out);
}

// round 12
// speedup vs baseline: 1.9864x; 1.0381x over previous
#include <cuda_runtime.h>
#include <cuda_bf16.h>
#include <cstdint>

// ---------------------------------------------------------------------------
// Problem constants: B=64, S=20, E=512, H=512, V=32000, C=1000
//   D1 = 11264, virtual K1 = 11776 = [enc|word|persona|h0], 4H = 2048
// ---------------------------------------------------------------------------
#define Bsz   64
#define Hdim  512
#define G4H   2048
#define Vdim  32000
#define K1v   11776

static __device__ float g_zpart[8 * Bsz * G4H];            // 4.2 MB (8 slices)
static __device__ float g_hbuf[2][Bsz * Hdim];
static __device__ float g_cbuf[2][Bsz * Hdim];
static __device__ float g_logits[Bsz * Vdim];              // 8.2 MB
static __device__ __nv_bfloat16 g_x1h[Bsz * K1v];          // layer-1 A hi
static __device__ __nv_bfloat16 g_x1l[Bsz * K1v];          // layer-1 A lo
static __device__ __nv_bfloat16 g_hh[2][Bsz * Hdim];       // h bf16 hi
static __device__ __nv_bfloat16 g_hl[2][Bsz * Hdim];       // h bf16 lo
static __device__ int g_bar1 = 0;                          // grid barrier arrive
static __device__ int g_bar2 = 0;                          // grid barrier depart

__device__ __forceinline__ float sigmoidf_fast(float x) {
    return 1.0f / (1.0f + __expf(-x));
}
__device__ __forceinline__ uint32_t smem_u32(const void* p) {
    uint32_t a;
    asm("{ .reg .u64 t; cvta.to.shared.u64 t, %1; cvt.u32.u64 %0, t; }"
        : "=r"(a) : "l"(p));
    return a;
}
__device__ __forceinline__ void ldsm4(uint32_t* r, uint32_t addr) {
    asm volatile("ldmatrix.sync.aligned.m8n8.x4.shared.b16 {%0,%1,%2,%3}, [%4];"
                 : "=r"(r[0]), "=r"(r[1]), "=r"(r[2]), "=r"(r[3]) : "r"(addr));
}
__device__ __forceinline__ void ldsm4t(uint32_t* r, uint32_t addr) {
    asm volatile("ldmatrix.sync.aligned.m8n8.x4.trans.shared.b16 {%0,%1,%2,%3}, [%4];"
                 : "=r"(r[0]), "=r"(r[1]), "=r"(r[2]), "=r"(r[3]) : "r"(addr));
}
__device__ __forceinline__ void mma16816(float* d, const uint32_t* a,
                                         uint32_t b0, uint32_t b1) {
    asm volatile(
        "mma.sync.aligned.m16n8k16.row.col.f32.bf16.bf16.f32 "
        "{%0,%1,%2,%3}, {%4,%5,%6,%7}, {%8,%9}, {%0,%1,%2,%3};"
        : "+f"(d[0]), "+f"(d[1]), "+f"(d[2]), "+f"(d[3])
        : "r"(a[0]), "r"(a[1]), "r"(a[2]), "r"(a[3]), "r"(b0), "r"(b1));
}
// Dekker split of 2 floats -> packed bf16x2 hi + lo (rn-exact vs element-wise)
__device__ __forceinline__ void dek2(float x, float y, uint32_t& hp, uint32_t& lp) {
    asm("cvt.rn.bf16x2.f32 %0, %1, %2;" : "=r"(hp) : "f"(y), "f"(x));
    float fx = __uint_as_float(hp << 16);
    float fy = __uint_as_float(hp & 0xFFFF0000u);
    asm("cvt.rn.bf16x2.f32 %0, %1, %2;" : "=r"(lp) : "f"(y - fy), "f"(x - fx));
}

// ---------------------------------------------------------------------------
// xconv: build layer-1 A = [enc|word|persona[spk]|h0] as bf16 hi/lo planes.
// ---------------------------------------------------------------------------
__global__ void xconv_kernel(const float* __restrict__ enc,
                             const float* __restrict__ word,
                             const float* __restrict__ persona,
                             const float* __restrict__ h0,
                             const int* __restrict__ speaker,
                             __nv_bfloat16* __restrict__ xh,
                             __nv_bfloat16* __restrict__ xl)
{
    int idx = blockIdx.x * 128 + threadIdx.x;      // < 94208
    int row = idx / (K1v / 8);
    int q = (idx - row * (K1v / 8)) * 8;
    const float* p;
    if (q < 10240)       p = enc + (long long)row * 10240 + q;
    else if (q < 10752)  p = word + (long long)row * 512 + (q - 10240);
    else if (q < 11264)  p = persona + (long long)speaker[row] * 512 + (q - 10752);
    else                 p = h0 + (long long)row * 512 + (q - 11264);
    float4 a = *reinterpret_cast<const float4*>(p);
    float4 b = *reinterpret_cast<const float4*>(p + 4);
    uint32_t h0p, l0p, h1p, l1p, h2p, l2p, h3p, l3p;
    dek2(a.x, a.y, h0p, l0p);
    dek2(a.z, a.w, h1p, l1p);
    dek2(b.x, b.y, h2p, l2p);
    dek2(b.z, b.w, h3p, l3p);
    long long o = (long long)row * K1v + q;
    *reinterpret_cast<uint4*>(xh + o) = make_uint4(h0p, h1p, h2p, h3p);
    *reinterpret_cast<uint4*>(xl + o) = make_uint4(l0p, l1p, l2p, l3p);
}

// ---------------------------------------------------------------------------
// bf16 Dekker-split warp-MMA GEMM, optionally FUSED with the LSTM gate
// reduction via an in-kernel grid barrier (NSL > 0).
//   Phase 1 (GEMM): Z[sp][m][n0+n] = sum_{k chunk} X[m][k] * Wv[k][n]
//   Phase 2 (NSL>0): grid barrier, then gates over all NSL slices:
//     c = sig(zf)*c_prev + sig(zi)*relu(zg); h = sig(zo)*relu(c)
// Grid-barrier requirement: ALL CTAs co-resident (grid <= 256; 2-3 CTA/SM fit).
// A: preconverted bf16 hi/lo planes (XSTRIDE row stride; WRAP: kg &= 511).
// W: fp32, converted in-loader. 3 Dekker streams into one fp32 acc set.
// ---------------------------------------------------------------------------
template<int XSTRIDE, bool WRAP, int NSL>
__global__ __launch_bounds__(128, 3) void mma_gemm_kernel(
    const __nv_bfloat16* __restrict__ Xh, const __nv_bfloat16* __restrict__ Xl,
    const float* __restrict__ Wa, const float* __restrict__ Wb, int wsplit,
    int kc, int N, float* __restrict__ Zall,
    const float* __restrict__ bias, const float* __restrict__ c_prev,
    float* __restrict__ c_new,
    uint32_t* __restrict__ hh_out, uint32_t* __restrict__ hl_out,
    float* __restrict__ h_mir, float* __restrict__ c_mir)
{
    __shared__ __align__(16) __nv_bfloat16 Ah[2][64][40];  // stride 80B
    __shared__ __align__(16) __nv_bfloat16 Al[2][64][40];
    __shared__ __align__(16) __nv_bfloat16 Bh[2][32][72];  // stride 144B
    __shared__ __align__(16) __nv_bfloat16 Bl[2][32][72];

    const int tid = threadIdx.x;
    const int lane = tid & 31;
    const int warp = tid >> 5;
    const int n0 = blockIdx.x * 64;
    const int sp = blockIdx.y;
    const int k0 = sp * kc;
    float* Z = Zall + (long long)sp * 64 * N;

    // A loader: row xm (0..63), k window xh2 in {0,16} (16 elements per thread)
    const int xm = tid >> 1;
    const int xh2 = (tid & 1) * 16;
    const __nv_bfloat16* xhp = Xh + (long long)xm * XSTRIDE;
    const __nv_bfloat16* xlp = Xl + (long long)xm * XSTRIDE;
    // B loader: k-row bk (0..31), n segment bn in {0,16,32,48}
    const int bk = tid >> 2;
    const int bn = (tid & 3) * 16;

    uint4 avh0, avh1, avl0, avl1;      // 16 bf16 per plane = 2 x uint4
    float4 br[4];
    auto loadA = [&](int t) {
        int kg = k0 + t * 32 + xh2;
        if (WRAP) kg &= 511;
        avh0 = *reinterpret_cast<const uint4*>(xhp + kg);
        avh1 = *reinterpret_cast<const uint4*>(xhp + kg + 8);
        avl0 = *reinterpret_cast<const uint4*>(xlp + kg);
        avl1 = *reinterpret_cast<const uint4*>(xlp + kg + 8);
    };
    auto loadB = [&](int t) {
        int r = k0 + t * 32 + bk;
        const float* p = (r < wsplit) ? (Wa + (long long)r * N)
                                      : (Wb + (long long)(r - wsplit) * N);
#pragma unroll
        for (int i = 0; i < 4; i++)
            br[i] = *reinterpret_cast<const float4*>(p + n0 + bn + i * 4);
    };
    auto storeA = [&](int b) {
        *reinterpret_cast<uint4*>(&Ah[b][xm][xh2])     = avh0;
        *reinterpret_cast<uint4*>(&Ah[b][xm][xh2 + 8]) = avh1;
        *reinterpret_cast<uint4*>(&Al[b][xm][xh2])     = avl0;
        *reinterpret_cast<uint4*>(&Al[b][xm][xh2 + 8]) = avl1;
    };
    auto storeB = [&](int b) {
#pragma unroll
        for (int i = 0; i < 4; i++) {
            float4 v = br[i];
            uint32_t h01, l01, h23, l23;
            dek2(v.x, v.y, h01, l01);
            dek2(v.z, v.w, h23, l23);
            *reinterpret_cast<uint2*>(&Bh[b][bk][bn + i * 4]) = make_uint2(h01, h23);
            *reinterpret_cast<uint2*>(&Bl[b][bk][bn + i * 4]) = make_uint2(l01, l23);
        }
    };

    float acc[4][2][4];
#pragma unroll
    for (int mt = 0; mt < 4; mt++)
#pragma unroll
        for (int nt = 0; nt < 2; nt++)
#pragma unroll
            for (int e = 0; e < 4; e++) acc[mt][nt][e] = 0.0f;

    const int NT = kc >> 5;     // BK = 32
    loadA(0); loadB(0);
    storeA(0); storeB(0);
    __syncthreads();

    const int nw = warp * 16;
    const int lr = lane & 15;
    const int lc = (lane >> 4) * 8;

    for (int t = 0; t < NT; t++) {
        const int buf = t & 1;
        const bool has_next = (t + 1 < NT);
        if (has_next) { loadA(t + 1); loadB(t + 1); }

#pragma unroll
        for (int s = 0; s < 2; s++) {
            uint32_t bhf[4], blf[4];
            ldsm4t(bhf, smem_u32(&Bh[buf][s * 16 + lr][nw + lc]));
            ldsm4t(blf, smem_u32(&Bl[buf][s * 16 + lr][nw + lc]));
#pragma unroll
            for (int mt = 0; mt < 4; mt++) {
                uint32_t ahf[4], alf[4];
                ldsm4(ahf, smem_u32(&Ah[buf][mt * 16 + lr][s * 16 + lc]));
                ldsm4(alf, smem_u32(&Al[buf][mt * 16 + lr][s * 16 + lc]));
                mma16816(acc[mt][0], ahf, bhf[0], bhf[1]);
                mma16816(acc[mt][1], ahf, bhf[2], bhf[3]);
                mma16816(acc[mt][0], ahf, blf[0], blf[1]);
                mma16816(acc[mt][1], ahf, blf[2], blf[3]);
                mma16816(acc[mt][0], alf, bhf[0], bhf[1]);
                mma16816(acc[mt][1], alf, bhf[2], bhf[3]);
            }
        }
        if (has_next) { storeA((t + 1) & 1); storeB((t + 1) & 1); }
        __syncthreads();
    }

    // GEMM epilogue: write split-K partials
#pragma unroll
    for (int mt = 0; mt < 4; mt++)
#pragma unroll
        for (int nt = 0; nt < 2; nt++) {
            int row = mt * 16 + (lane >> 2);
            int col = n0 + nw + nt * 8 + (lane & 3) * 2;
            *reinterpret_cast<float2*>(&Z[(long long)row * N + col]) =
                make_float2(acc[mt][nt][0], acc[mt][nt][1]);
            *reinterpret_cast<float2*>(&Z[(long long)(row + 8) * N + col]) =
                make_float2(acc[mt][nt][2], acc[mt][nt][3]);
        }

    if (NSL > 0) {
        // ---- grid barrier (all CTAs co-resident by construction) ----
        const int G = gridDim.x * gridDim.y;
        __threadfence();
        __syncthreads();
        if (tid == 0) {
            atomicAdd(&g_bar1, 1);
            while (*(volatile int*)&g_bar1 < G) {}
        }
        __syncthreads();
        __threadfence();

        // ---- phase 2: gates over all slices ----
        int gid = (blockIdx.y * gridDim.x + blockIdx.x) * 128 + tid;
        if (gid < Bsz * (Hdim / 2)) {
            int bt = gid >> 8;
            int j = (gid & 255) * 2;
            float2 zi = *reinterpret_cast<const float2*>(bias + j);
            float2 zf = *reinterpret_cast<const float2*>(bias + 512 + j);
            float2 zg = *reinterpret_cast<const float2*>(bias + 1024 + j);
            float2 zo = *reinterpret_cast<const float2*>(bias + 1536 + j);
            const float* p = Zall + (long long)bt * G4H + j;
#pragma unroll
            for (int s = 0; s < NSL; s++) {
                const float* q = p + (long long)s * Bsz * G4H;
                float2 a = *reinterpret_cast<const float2*>(q);
                float2 b = *reinterpret_cast<const float2*>(q + 512);
                float2 c = *reinterpret_cast<const float2*>(q + 1024);
                float2 d = *reinterpret_cast<const float2*>(q + 1536);
                zi.x += a.x; zi.y += a.y;
                zf.x += b.x; zf.y += b.y;
                zg.x += c.x; zg.y += c.y;
                zo.x += d.x; zo.y += d.y;
            }
            int idx = bt * Hdim + j;
            float2 cp = *reinterpret_cast<const float2*>(c_prev + idx);
            float2 cv, hv;
            cv.x = sigmoidf_fast(zf.x) * cp.x + sigmoidf_fast(zi.x) * fmaxf(zg.x, 0.0f);
            cv.y = sigmoidf_fast(zf.y) * cp.y + sigmoidf_fast(zi.y) * fmaxf(zg.y, 0.0f);
            hv.x = sigmoidf_fast(zo.x) * fmaxf(cv.x, 0.0f);
            hv.y = sigmoidf_fast(zo.y) * fmaxf(cv.y, 0.0f);
            *reinterpret_cast<float2*>(c_new + idx) = cv;
            uint32_t hp, lp;
            dek2(hv.x, hv.y, hp, lp);
            hh_out[gid] = hp;
            hl_out[gid] = lp;
            if (h_mir) {
                *reinterpret_cast<float2*>(h_mir + idx) = hv;
                *reinterpret_cast<float2*>(c_mir + idx) = cv;
            }
        }

        // ---- depart barrier + counter reset (CTA (0,0)) ----
        __threadfence();
        __syncthreads();
        if (tid == 0) {
            atomicAdd(&g_bar2, 1);
            if (blockIdx.x == 0 && blockIdx.y == 0) {
                while (*(volatile int*)&g_bar2 < G) {}
                atomicExch(&g_bar1, 0);
                atomicExch(&g_bar2, 0);
            }
        }
    }
}

// ---------------------------------------------------------------------------
// Softmax over V=32000 per batch row
// ---------------------------------------------------------------------------
__global__ void softmax_kernel(const float* __restrict__ L,
                               const float* __restrict__ bd,
                               float* __restrict__ out)
{
    const int V = Vdim;
    int b = blockIdx.x;
    int tid = threadIdx.x;
    const float* r0 = L + (long long)b * V;

    float m = -1e30f, s = 0.0f;
    for (int v = tid; v < V; v += 512) {
        float val = r0[v] + bd[v];
        float nm = fmaxf(m, val);
        s = s * __expf(m - nm) + __expf(val - nm);
        m = nm;
    }
    __shared__ float sm[512], ss[512];
    sm[tid] = m; ss[tid] = s;
    __syncthreads();
    for (int st = 256; st > 0; st >>= 1) {
        if (tid < st) {
            float m2 = sm[tid + st], s2 = ss[tid + st];
            float nm = fmaxf(sm[tid], m2);
            ss[tid] = ss[tid] * __expf(sm[tid] - nm) + s2 * __expf(m2 - nm);
            sm[tid] = nm;
        }
        __syncthreads();
    }
    float M = sm[0];
    float Sinv = 1.0f / ss[0];
    for (int v = tid; v < V; v += 512) {
        float val = r0[v] + bd[v];
        out[(long long)b * V + v] = __expf(val - M) * Sinv;
    }
}

// ---------------------------------------------------------------------------
// kernel_launch
// ---------------------------------------------------------------------------
extern "C" void kernel_launch(void* const* d_in, const int* in_sizes, int n_in,
                              void* d_out, int out_size)
{
    const float* enc     = (const float*)d_in[0];
    const float* word    = (const float*)d_in[1];
    const float* h0      = (const float*)d_in[2];
    const float* c0      = (const float*)d_in[3];
    const float* persona = (const float*)d_in[4];
    const float* W1      = (const float*)d_in[5];
    const float* U1      = (const float*)d_in[6];
    const float* b1      = (const float*)d_in[7];
    const float* W2      = (const float*)d_in[8];
    const float* U2      = (const float*)d_in[9];
    const float* b2      = (const float*)d_in[10];
    const float* W3      = (const float*)d_in[11];
    const float* U3      = (const float*)d_in[12];
    const float* b3      = (const float*)d_in[13];
    const float* W4      = (const float*)d_in[14];
    const float* U4      = (const float*)d_in[15];
    const float* b4      = (const float*)d_in[16];
    const float* Wd      = (const float*)d_in[17];
    const float* bd      = (const float*)d_in[18];
    const int*   speaker = (const int*)d_in[19];
    float* out = (float*)d_out;

    void *pz, *pc, *pl, *pxh, *pxl, *phh, *phl;
    cudaGetSymbolAddress(&pz, g_zpart);
    cudaGetSymbolAddress(&pc, g_cbuf);
    cudaGetSymbolAddress(&pl, g_logits);
    cudaGetSymbolAddress(&pxh, g_x1h);
    cudaGetSymbolAddress(&pxl, g_x1l);
    cudaGetSymbolAddress(&phh, g_hh);
    cudaGetSymbolAddress(&phl, g_hl);
    float* zp = (float*)pz;
    float* cb = (float*)pc;
    float* lg = (float*)pl;
    __nv_bfloat16* x1h = (__nv_bfloat16*)pxh;
    __nv_bfloat16* x1l = (__nv_bfloat16*)pxl;
    __nv_bfloat16* hh0 = (__nv_bfloat16*)phh;
    __nv_bfloat16* hh1 = hh0 + Bsz * Hdim;
    __nv_bfloat16* hl0 = (__nv_bfloat16*)phl;
    __nv_bfloat16* hl1 = hl0 + Bsz * Hdim;
    float* c1b = cb;
    float* c2b = cb + Bsz * Hdim;

    // 0) layer-1 A -> bf16 hi/lo planes
    xconv_kernel<<<(Bsz * K1v / 8 + 127) / 128, 128>>>(
        enc, word, persona, h0, speaker, x1h, x1l);

    // 1) layer 1 (fused gates): K=11776, 8 splits of 1472, grid 32x8=256
    mma_gemm_kernel<K1v, false, 8><<<dim3(32, 8), 128>>>(
        x1h, x1l, W1, U1, 11264, 1472, G4H, zp,
        b1, c0, c1b, (uint32_t*)hh0, (uint32_t*)hl0, nullptr, nullptr);

    // 2) layers 2..4 (fused gates): K=1024, 8 splits of 128, grid 32x8=256
    mma_gemm_kernel<Hdim, true, 8><<<dim3(32, 8), 128>>>(
        hh0, hl0, W2, U2, 512, 128, G4H, zp,
        b2, c1b, c2b, (uint32_t*)hh1, (uint32_t*)hl1, nullptr, nullptr);

    mma_gemm_kernel<Hdim, true, 8><<<dim3(32, 8), 128>>>(
        hh1, hl1, W3, U3, 512, 128, G4H, zp,
        b3, c2b, c1b, (uint32_t*)hh0, (uint32_t*)hl0, nullptr, nullptr);

    mma_gemm_kernel<Hdim, true, 8><<<dim3(32, 8), 128>>>(
        hh0, hl0, W4, U4, 512, 128, G4H, zp,
        b4, c1b, c2b, (uint32_t*)hh1, (uint32_t*)hl1,
        out + (long long)Bsz * Vdim,
        out + (long long)Bsz * Vdim + Bsz * Hdim);

    // 3) decoder: logits = h4 @ Wd, grid 500, no split-K, no fusion
    mma_gemm_kernel<Hdim, true, 0><<<dim3(500, 1), 128>>>(
        hh1, hl1, Wd, Wd, 1 << 30, 512, Vdim, lg,
        nullptr, nullptr, nullptr, nullptr, nullptr, nullptr, nullptr);

    // 4) softmax -> probs
    softmax_kernel<<<Bsz, 512>>>(lg, bd, out);
}